// round 14
// baseline (speedup 1.0000x reference)
#include <cuda_runtime.h>
#include <math.h>
#include <stdint.h>

#define GD 60
#define GG 3600
#define NT 512

// shared memory layout (floats):
//   x_s  @ 0     : 32*104 = 3328   (tf32 bits, k-permuted)
//   wbuf @ 3328  : 384*104 = 39936 (gates W; heads W 192*136=26112 fits)
//   h_s  @ 43264 : 32*136 = 4352   (tf32 bits, k-permuted; phase-A hwarp overlays)
//   hid  @ 47616 : 32*196 = 6272
//   fin  @ 53888 : 160
#define XS_OFF   0
#define WB_OFF   3328
#define HS_OFF   43264
#define HID_OFF  47616
#define FIN_OFF  53888
#define SMEM_FLOATS 54048
#define SMEM_BYTES (SMEM_FLOATS * 4)

struct Params {
    const float* mv;
    const float* boxes;
    const float* W_stats; const float* b_stats; const float* g_stats; const float* be_stats;
    const float* W_b1;    const float* b_b1;    const float* g_b1;    const float* be_b1;
    const float* W_b2;    const float* b_b2;    const float* g_b2;    const float* be_b2;
    const float* W_ih;    const float* W_hh;    const float* b_ih;    const float* b_hh;
    const float* W_p1;    const float* b_p1;    const float* W_p2;    const float* b_p2;
    const float* W_s1;    const float* b_s1;    const float* W_s2;    const float* b_s2;
    const float* W_c1;    const float* b_c1;    const float* W_c2;    const float* b_c2;
    float* out;
};

__device__ __forceinline__ float tanhfast(float x) {
    float y;
    asm("tanh.approx.f32 %0, %1;" : "=f"(y) : "f"(x));
    return y;
}
__device__ __forceinline__ float sigfast(float x) {
    return fmaf(0.5f, tanhfast(0.5f * x), 0.5f);
}
__device__ __forceinline__ uint32_t tf32cvt(float x) {
    uint32_t r;
    asm("cvt.rna.tf32.f32 %0, %1;" : "=r"(r) : "f"(x));
    return r;
}
// within each 8-k block: k<4 -> 2k ; k>=4 -> 2(k-4)+1   (pairs (k,k+4) adjacent)
__device__ __forceinline__ int permk(int c) {
    return (c & ~7) | ((c & 3) << 1) | ((c & 4) >> 2);
}
// convert+permute one 8-float block in smem (in place): thread owns the block
__device__ __forceinline__ void cvtperm8(float* base) {
    float4 lo = *(float4*)base;          // k0..k3
    float4 hi = *(float4*)(base + 4);    // k4..k7
    uint4 o0, o1;
    o0.x = tf32cvt(lo.x); o0.y = tf32cvt(hi.x);
    o0.z = tf32cvt(lo.y); o0.w = tf32cvt(hi.y);
    o1.x = tf32cvt(lo.z); o1.y = tf32cvt(hi.z);
    o1.z = tf32cvt(lo.w); o1.w = tf32cvt(hi.w);
    *(uint4*)base = o0;
    *(uint4*)(base + 4) = o1;
}
__device__ __forceinline__ void mma_tf32(float* d,
                                         uint32_t a0, uint32_t a1, uint32_t a2, uint32_t a3,
                                         uint32_t b0, uint32_t b1) {
    asm volatile(
        "mma.sync.aligned.m16n8k8.row.col.f32.tf32.tf32.f32 "
        "{%0,%1,%2,%3}, {%4,%5,%6,%7}, {%8,%9}, {%0,%1,%2,%3};"
        : "+f"(d[0]), "+f"(d[1]), "+f"(d[2]), "+f"(d[3])
        : "r"(a0), "r"(a1), "r"(a2), "r"(a3), "r"(b0), "r"(b1));
}
__device__ __forceinline__ void cp16(void* dst, const void* src) {
    unsigned saddr = (unsigned)__cvta_generic_to_shared(dst);
    asm volatile("cp.async.cg.shared.global [%0], [%1], 16;" :: "r"(saddr), "l"(src));
}
// packed gates col c -> original W_ih row (f-gate skipped, (i,g,o) interleaved per unit pair)
__device__ __forceinline__ int gates_row(int c) {
    int ng = c / 48, cl = c % 48;
    int j = cl >> 3, r = cl & 7;
    int gate = j % 3;
    int u = 16 * ng + 8 * (j / 3) + r;
    return (gate == 0) ? u : (gate == 1) ? 256 + u : 384 + u;
}

__global__ void __launch_bounds__(NT, 1)
tracker_fused_kernel(Params p) {
    extern __shared__ float smem[];
    uint32_t* x_u    = (uint32_t*)(smem + XS_OFF);
    float*    wbuf   = smem + WB_OFF;
    uint32_t* wbuf_u = (uint32_t*)wbuf;
    uint32_t* h_u    = (uint32_t*)(smem + HS_OFF);
    float*    hwarp  = smem + HS_OFF;      // phase-A overlay (1024 floats)
    float*    hid_s  = smem + HID_OFF;
    float*    fin_s  = smem + FIN_OFF;

    const int tid  = threadIdx.x;
    const int lane = tid & 31;
    const int w    = tid >> 5;        // 0..15
    const int gid  = lane >> 2;       // 0..7
    const int tig  = lane & 3;        // 0..3
    const int box0 = blockIdx.x * 32;

    // ---- stage gates W fp32 with packed-row mapping (k-linear) ----
    #pragma unroll
    for (int it = 0; it < 18; it++) {
        int idx = tid + it * NT;
        int c = idx / 24, k4 = idx % 24;
        cp16(wbuf + c * 104 + 4 * k4, p.W_ih + gates_row(c) * 96 + 4 * k4);
    }
    asm volatile("cp.async.commit_group;");

    // ============ Phase A: boxes 2w, 2w+1 interleaved -> x_u (tf32, permuted) ============
    {
        const int b0 = 2 * w, b1 = 2 * w + 1;

        const float* wsaP = p.W_stats + lane * 6;
        const float* wsbP = p.W_stats + (lane + 32) * 6;
        float ws_a[6], ws_b[6];
        #pragma unroll
        for (int k = 0; k < 6; k++) { ws_a[k] = __ldg(wsaP + k); ws_b[k] = __ldg(wsbP + k); }
        float bs_a  = __ldg(p.b_stats + lane),  bs_b  = __ldg(p.b_stats + lane + 32);
        float gs_a  = __ldg(p.g_stats + lane),  gs_b  = __ldg(p.g_stats + lane + 32);
        float bes_a = __ldg(p.be_stats + lane), bes_b = __ldg(p.be_stats + lane + 32);
        float4 wb1v = __ldg((const float4*)(p.W_b1) + lane);
        float bb1 = __ldg(p.b_b1 + lane), gb1 = __ldg(p.g_b1 + lane), beb1 = __ldg(p.be_b1 + lane);
        float bb2 = __ldg(p.b_b2 + lane), gb2 = __ldg(p.g_b2 + lane), beb2 = __ldg(p.be_b2 + lane);

        float4 bxA = __ldg((const float4*)p.boxes + (box0 + b0));
        float4 bxB = __ldg((const float4*)p.boxes + (box0 + b1));
        float anA0 = fminf(fmaxf(bxA.x * (1.0f / 960.0f), 0.0f), 1.0f);
        float anA1 = fminf(fmaxf(bxA.y * (1.0f / 960.0f), 0.0f), 1.0f);
        float anA2 = fminf(fmaxf(bxA.z * (1.0f / 960.0f), 0.0f), 1.0f);
        float anA3 = fminf(fmaxf(bxA.w * (1.0f / 960.0f), 0.0f), 1.0f);
        float anB0 = fminf(fmaxf(bxB.x * (1.0f / 960.0f), 0.0f), 1.0f);
        float anB1 = fminf(fmaxf(bxB.y * (1.0f / 960.0f), 0.0f), 1.0f);
        float anB2 = fminf(fmaxf(bxB.z * (1.0f / 960.0f), 0.0f), 1.0f);
        float anB3 = fminf(fmaxf(bxB.w * (1.0f / 960.0f), 0.0f), 1.0f);

        int xA1 = min(max((int)floorf(anA0 * 60.0f), 0), GD - 1);
        int yA1 = min(max((int)floorf(anA1 * 60.0f), 0), GD - 1);
        int xA2 = min(max((int)ceilf(anA2 * 60.0f), xA1 + 1), GD);
        int yA2 = min(max((int)ceilf(anA3 * 60.0f), yA1 + 1), GD);
        int xB1 = min(max((int)floorf(anB0 * 60.0f), 0), GD - 1);
        int yB1 = min(max((int)floorf(anB1 * 60.0f), 0), GD - 1);
        int xB2 = min(max((int)ceilf(anB2 * 60.0f), xB1 + 1), GD);
        int yB2 = min(max((int)ceilf(anB3 * 60.0f), yB1 + 1), GD);
        int wdA = xA2 - xA1, areaA = wdA * (yA2 - yA1);
        int wdB = xB2 - xB1, areaB = wdB * (yB2 - yB1);
        int maxArea = max(areaA, areaB);

        float sA0 = 0.f, sA1 = 0.f, qA0 = 0.f, qA1 = 0.f;
        float mxA0 = -1e30f, mxA1 = -1e30f, mnA0 = 1e30f, mnA1 = 1e30f;
        float sB0 = 0.f, sB1 = 0.f, qB0 = 0.f, qB1 = 0.f;
        float mxB0 = -1e30f, mxB1 = -1e30f, mnB0 = 1e30f, mnB1 = 1e30f;

        for (int c = lane; c < maxArea; c += 32) {
            if (c < areaA) {
                int ry = c / wdA;
                int idx = (yA1 + ry) * GD + xA1 + (c - ry * wdA);
                float v0 = __ldg(p.mv + idx);
                float v1 = __ldg(p.mv + GG + idx);
                sA0 += v0; qA0 += v0 * v0; mxA0 = fmaxf(mxA0, v0); mnA0 = fminf(mnA0, v0);
                sA1 += v1; qA1 += v1 * v1; mxA1 = fmaxf(mxA1, v1); mnA1 = fminf(mnA1, v1);
            }
            if (c < areaB) {
                int ry = c / wdB;
                int idx = (yB1 + ry) * GD + xB1 + (c - ry * wdB);
                float v0 = __ldg(p.mv + idx);
                float v1 = __ldg(p.mv + GG + idx);
                sB0 += v0; qB0 += v0 * v0; mxB0 = fmaxf(mxB0, v0); mnB0 = fminf(mnB0, v0);
                sB1 += v1; qB1 += v1 * v1; mxB1 = fmaxf(mxB1, v1); mnB1 = fminf(mnB1, v1);
            }
        }
        #pragma unroll
        for (int o = 16; o; o >>= 1) {
            sA0 += __shfl_xor_sync(0xffffffffu, sA0, o);
            sA1 += __shfl_xor_sync(0xffffffffu, sA1, o);
            qA0 += __shfl_xor_sync(0xffffffffu, qA0, o);
            qA1 += __shfl_xor_sync(0xffffffffu, qA1, o);
            sB0 += __shfl_xor_sync(0xffffffffu, sB0, o);
            sB1 += __shfl_xor_sync(0xffffffffu, sB1, o);
            qB0 += __shfl_xor_sync(0xffffffffu, qB0, o);
            qB1 += __shfl_xor_sync(0xffffffffu, qB1, o);
            mxA0 = fmaxf(mxA0, __shfl_xor_sync(0xffffffffu, mxA0, o));
            mxA1 = fmaxf(mxA1, __shfl_xor_sync(0xffffffffu, mxA1, o));
            mnA0 = fminf(mnA0, __shfl_xor_sync(0xffffffffu, mnA0, o));
            mnA1 = fminf(mnA1, __shfl_xor_sync(0xffffffffu, mnA1, o));
            mxB0 = fmaxf(mxB0, __shfl_xor_sync(0xffffffffu, mxB0, o));
            mxB1 = fmaxf(mxB1, __shfl_xor_sync(0xffffffffu, mxB1, o));
            mnB0 = fminf(mnB0, __shfl_xor_sync(0xffffffffu, mnB0, o));
            mnB1 = fminf(mnB1, __shfl_xor_sync(0xffffffffu, mnB1, o));
        }
        float rcA = __fdividef(1.0f, (float)areaA);
        float rcB = __fdividef(1.0f, (float)areaB);
        float mA0 = sA0 * rcA, mA1 = sA1 * rcA;
        float mB0 = sB0 * rcB, mB1 = sB1 * rcB;
        float stA[6], stB[6];
        stA[0] = mA0; stA[1] = mA1;
        stA[2] = sqrtf(fmaxf(qA0 * rcA - mA0 * mA0, 0.0f));
        stA[3] = sqrtf(fmaxf(qA1 * rcA - mA1 * mA1, 0.0f));
        stA[4] = mxA0 - mnA0; stA[5] = mxA1 - mnA1;
        stB[0] = mB0; stB[1] = mB1;
        stB[2] = sqrtf(fmaxf(qB0 * rcB - mB0 * mB0, 0.0f));
        stB[3] = sqrtf(fmaxf(qB1 * rcB - mB1 * mB1, 0.0f));
        stB[4] = mxB0 - mnB0; stB[5] = mxB1 - mnB1;

        float zAa = bs_a, zAb = bs_b, zBa = bs_a, zBb = bs_b;
        #pragma unroll
        for (int k = 0; k < 6; k++) {
            zAa = fmaf(stA[k], ws_a[k], zAa);
            zAb = fmaf(stA[k], ws_b[k], zAb);
            zBa = fmaf(stB[k], ws_a[k], zBa);
            zBb = fmaf(stB[k], ws_b[k], zBb);
        }
        {
            float sA = zAa + zAb, qA = zAa * zAa + zAb * zAb;
            float sB = zBa + zBb, qB = zBa * zBa + zBb * zBb;
            #pragma unroll
            for (int o = 16; o; o >>= 1) {
                sA += __shfl_xor_sync(0xffffffffu, sA, o);
                qA += __shfl_xor_sync(0xffffffffu, qA, o);
                sB += __shfl_xor_sync(0xffffffffu, sB, o);
                qB += __shfl_xor_sync(0xffffffffu, qB, o);
            }
            float muA = sA * (1.0f / 64.0f);
            float invA = rsqrtf(fmaxf(qA * (1.0f / 64.0f) - muA * muA, 0.0f) + 1e-5f);
            float muB = sB * (1.0f / 64.0f);
            float invB = rsqrtf(fmaxf(qB * (1.0f / 64.0f) - muB * muB, 0.0f) + 1e-5f);
            x_u[b0 * 104 + permk(lane)]      = tf32cvt(fmaxf(fmaf((zAa - muA) * invA, gs_a, bes_a), 0.0f));
            x_u[b0 * 104 + permk(lane + 32)] = tf32cvt(fmaxf(fmaf((zAb - muA) * invA, gs_b, bes_b), 0.0f));
            x_u[b1 * 104 + permk(lane)]      = tf32cvt(fmaxf(fmaf((zBa - muB) * invB, gs_a, bes_a), 0.0f));
            x_u[b1 * 104 + permk(lane + 32)] = tf32cvt(fmaxf(fmaf((zBb - muB) * invB, gs_b, bes_b), 0.0f));
        }

        float tA = bb1, tB = bb1;
        tA = fmaf(anA0, wb1v.x, tA); tB = fmaf(anB0, wb1v.x, tB);
        tA = fmaf(anA1, wb1v.y, tA); tB = fmaf(anB1, wb1v.y, tB);
        tA = fmaf(anA2, wb1v.z, tA); tB = fmaf(anB2, wb1v.z, tB);
        tA = fmaf(anA3, wb1v.w, tA); tB = fmaf(anB3, wb1v.w, tB);
        {
            float sA = tA, qA = tA * tA, sB = tB, qB = tB * tB;
            #pragma unroll
            for (int o = 16; o; o >>= 1) {
                sA += __shfl_xor_sync(0xffffffffu, sA, o);
                qA += __shfl_xor_sync(0xffffffffu, qA, o);
                sB += __shfl_xor_sync(0xffffffffu, sB, o);
                qB += __shfl_xor_sync(0xffffffffu, qB, o);
            }
            float muA = sA * (1.0f / 32.0f);
            float invA = rsqrtf(fmaxf(qA * (1.0f / 32.0f) - muA * muA, 0.0f) + 1e-5f);
            float muB = sB * (1.0f / 32.0f);
            float invB = rsqrtf(fmaxf(qB * (1.0f / 32.0f) - muB * muB, 0.0f) + 1e-5f);
            hwarp[b0 * 32 + lane] = fmaxf(fmaf((tA - muA) * invA, gb1, beb1), 0.0f);
            hwarp[b1 * 32 + lane] = fmaxf(fmaf((tB - muB) * invB, gb1, beb1), 0.0f);
        }
        __syncwarp();
        float tA0 = bb2, tA1 = 0.0f, tB0 = bb2, tB1 = 0.0f;
        const float* wb2 = p.W_b2 + lane * 32;
        #pragma unroll
        for (int k4 = 0; k4 < 8; k4 += 2) {
            float4 wva = __ldg((const float4*)wb2 + k4);
            float4 wvb = __ldg((const float4*)wb2 + k4 + 1);
            const float* hpA = hwarp + b0 * 32 + 4 * k4;
            const float* hpB = hwarp + b1 * 32 + 4 * k4;
            tA0 = fmaf(hpA[0], wva.x, tA0); tB0 = fmaf(hpB[0], wva.x, tB0);
            tA0 = fmaf(hpA[1], wva.y, tA0); tB0 = fmaf(hpB[1], wva.y, tB0);
            tA0 = fmaf(hpA[2], wva.z, tA0); tB0 = fmaf(hpB[2], wva.z, tB0);
            tA0 = fmaf(hpA[3], wva.w, tA0); tB0 = fmaf(hpB[3], wva.w, tB0);
            tA1 = fmaf(hpA[4], wvb.x, tA1); tB1 = fmaf(hpB[4], wvb.x, tB1);
            tA1 = fmaf(hpA[5], wvb.y, tA1); tB1 = fmaf(hpB[5], wvb.y, tB1);
            tA1 = fmaf(hpA[6], wvb.z, tA1); tB1 = fmaf(hpB[6], wvb.z, tB1);
            tA1 = fmaf(hpA[7], wvb.w, tA1); tB1 = fmaf(hpB[7], wvb.w, tB1);
        }
        __syncwarp();
        {
            float t2A = tA0 + tA1, t2B = tB0 + tB1;
            float sA = t2A, qA = t2A * t2A, sB = t2B, qB = t2B * t2B;
            #pragma unroll
            for (int o = 16; o; o >>= 1) {
                sA += __shfl_xor_sync(0xffffffffu, sA, o);
                qA += __shfl_xor_sync(0xffffffffu, qA, o);
                sB += __shfl_xor_sync(0xffffffffu, sB, o);
                qB += __shfl_xor_sync(0xffffffffu, qB, o);
            }
            float muA = sA * (1.0f / 32.0f);
            float invA = rsqrtf(fmaxf(qA * (1.0f / 32.0f) - muA * muA, 0.0f) + 1e-5f);
            float muB = sB * (1.0f / 32.0f);
            float invB = rsqrtf(fmaxf(qB * (1.0f / 32.0f) - muB * muB, 0.0f) + 1e-5f);
            x_u[b0 * 104 + permk(64 + lane)] = tf32cvt(fmaxf(fmaf((t2A - muA) * invA, gb2, beb2), 0.0f));
            x_u[b1 * 104 + permk(64 + lane)] = tf32cvt(fmaxf(fmaf((t2B - muB) * invB, gb2, beb2), 0.0f));
        }
    }

    asm volatile("cp.async.wait_group 0;");
    __syncthreads();   // x_u complete + gates W (fp32) staged

    // ---- convert+permute gates W in smem: 384 rows x 12 blocks = 4608 ----
    #pragma unroll
    for (int it = 0; it < 9; it++) {
        int idx = tid + it * NT;
        int n = idx / 12, blk = idx % 12;
        cvtperm8(wbuf + n * 104 + 8 * blk);
    }
    __syncthreads();

    // ============ Gates GEMM via tf32 mma (LDS.64 fragments) ============
    const int mt = w & 1;         // M-tile (16 boxes)
    const int ng = w >> 1;        // 48 packed cols = 16 hidden units x (i,g,o)
    const int m0 = mt * 16;

    float dacc[6][4];
    #pragma unroll
    for (int j = 0; j < 6; j++)
        #pragma unroll
        for (int q = 0; q < 4; q++) dacc[j][q] = 0.0f;

    #pragma unroll
    for (int ks = 0; ks < 12; ks++) {
        int k0 = 8 * ks;
        uint2 aA = *(const uint2*)(x_u + (m0 + gid) * 104 + k0 + 2 * tig);      // (a0,a2)
        uint2 aB = *(const uint2*)(x_u + (m0 + gid + 8) * 104 + k0 + 2 * tig);  // (a1,a3)
        #pragma unroll
        for (int j = 0; j < 6; j++) {
            int n = ng * 48 + 8 * j + gid;
            uint2 bv = *(const uint2*)(wbuf_u + n * 104 + k0 + 2 * tig);        // (b0,b1)
            mma_tf32(dacc[j], aA.x, aB.x, aA.y, aB.y, bv.x, bv.y);
        }
    }
    __syncthreads();   // gates-W reads done -> wbuf reusable

    // ---- stage heads W fp32 (k-linear): 6144 float4 ----
    #pragma unroll
    for (int it = 0; it < 12; it++) {
        int idx = tid + it * NT;
        int n = idx >> 5, k4 = idx & 31;
        const float* src = (n < 64) ? (p.W_p1 + n * 128)
                         : (n < 128) ? (p.W_s1 + (n - 64) * 128)
                                     : (p.W_c1 + (n - 128) * 128);
        cp16(wbuf + n * 136 + 4 * k4, src + 4 * k4);
    }
    asm volatile("cp.async.commit_group;");

    // ============ LSTM fully in registers -> h_u (tf32, permuted) ============
    #pragma unroll
    for (int jj = 0; jj < 2; jj++) {
        #pragma unroll
        for (int e = 0; e < 2; e++) {
            int u = 16 * ng + 8 * jj + 2 * tig + e;
            float bi = __ldg(p.b_ih + u)       + __ldg(p.b_hh + u);
            float bg = __ldg(p.b_ih + 256 + u) + __ldg(p.b_hh + 256 + u);
            float bo = __ldg(p.b_ih + 384 + u) + __ldg(p.b_hh + 384 + u);
            {
                float iv = dacc[3 * jj + 0][e] + bi;
                float gv = dacc[3 * jj + 1][e] + bg;
                float ov = dacc[3 * jj + 2][e] + bo;
                float c = sigfast(iv) * tanhfast(gv);
                h_u[(m0 + gid) * 136 + permk(u)] = tf32cvt(sigfast(ov) * tanhfast(c));
            }
            {
                float iv = dacc[3 * jj + 0][2 + e] + bi;
                float gv = dacc[3 * jj + 1][2 + e] + bg;
                float ov = dacc[3 * jj + 2][2 + e] + bo;
                float c = sigfast(iv) * tanhfast(gv);
                h_u[(m0 + gid + 8) * 136 + permk(u)] = tf32cvt(sigfast(ov) * tanhfast(c));
            }
        }
    }

    asm volatile("cp.async.wait_group 0;");
    __syncthreads();   // h complete + heads W (fp32) staged

    // ---- convert+permute heads W in smem: 192 rows x 16 blocks = 3072 ----
    #pragma unroll
    for (int it = 0; it < 6; it++) {
        int idx = tid + it * NT;
        int n = idx >> 4, blk = idx & 15;
        cvtperm8(wbuf + n * 136 + 8 * blk);
    }
    __syncthreads();

    // ============ Heads GEMM via tf32 mma (LDS.64 fragments) ============
    float hacc[3][4];
    #pragma unroll
    for (int j = 0; j < 3; j++)
        #pragma unroll
        for (int q = 0; q < 4; q++) hacc[j][q] = 0.0f;

    #pragma unroll
    for (int ks = 0; ks < 16; ks++) {
        int k0 = 8 * ks;
        uint2 aA = *(const uint2*)(h_u + (m0 + gid) * 136 + k0 + 2 * tig);
        uint2 aB = *(const uint2*)(h_u + (m0 + gid + 8) * 136 + k0 + 2 * tig);
        #pragma unroll
        for (int j = 0; j < 3; j++) {
            int n = ng * 24 + 8 * j + gid;
            uint2 bv = *(const uint2*)(wbuf_u + n * 136 + k0 + 2 * tig);
            mma_tf32(hacc[j], aA.x, aB.x, aA.y, aB.y, bv.x, bv.y);
        }
    }

    // ---- epilogue: bias + relu -> hid_s [32][196] ----
    #pragma unroll
    for (int j = 0; j < 3; j++) {
        int nc = ng * 24 + 8 * j + 2 * tig;
        float bias0 = (nc < 64) ? __ldg(p.b_p1 + nc)
                    : (nc < 128) ? __ldg(p.b_s1 + nc - 64)
                                 : __ldg(p.b_c1 + nc - 128);
        int nc1 = nc + 1;
        float bias1 = (nc1 < 64) ? __ldg(p.b_p1 + nc1)
                    : (nc1 < 128) ? __ldg(p.b_s1 + nc1 - 64)
                                  : __ldg(p.b_c1 + nc1 - 128);
        *(float2*)(hid_s + (m0 + gid) * 196 + nc) =
            make_float2(fmaxf(hacc[j][0] + bias0, 0.0f), fmaxf(hacc[j][1] + bias1, 0.0f));
        *(float2*)(hid_s + (m0 + gid + 8) * 196 + nc) =
            make_float2(fmaxf(hacc[j][2] + bias0, 0.0f), fmaxf(hacc[j][3] + bias1, 0.0f));
    }
    __syncthreads();

    // ============ Head second layers (5 scalars per box) ============
    if (tid < 160) {
        int b = tid / 5, o = tid % 5;
        const float* hp = hid_s + b * 196 + ((o < 2) ? 0 : (o < 4) ? 64 : 128);
        const float* wp;
        float a;
        if (o == 0)      { wp = p.W_p2;      a = __ldg(p.b_p2); }
        else if (o == 1) { wp = p.W_p2 + 64; a = __ldg(p.b_p2 + 1); }
        else if (o == 2) { wp = p.W_s2;      a = __ldg(p.b_s2); }
        else if (o == 3) { wp = p.W_s2 + 64; a = __ldg(p.b_s2 + 1); }
        else             { wp = p.W_c2;      a = __ldg(p.b_c2); }
        #pragma unroll
        for (int k4 = 0; k4 < 16; k4++) {
            float4 hv = *(const float4*)(hp + 4 * k4);
            float4 wv = __ldg((const float4*)wp + k4);
            a = fmaf(hv.x, wv.x, a);
            a = fmaf(hv.y, wv.y, a);
            a = fmaf(hv.z, wv.z, a);
            a = fmaf(hv.w, wv.w, a);
        }
        fin_s[b * 5 + o] = a;
    }
    __syncthreads();

    // ============ Decode + output ============
    if (tid < 32) {
        int b = tid;
        float4 bx = __ldg((const float4*)p.boxes + (box0 + b));
        float cx = (bx.x + bx.z) * 0.5f, cy = (bx.y + bx.w) * 0.5f;
        float wd = bx.z - bx.x, hg = bx.w - bx.y;
        float ncx = cx + fin_s[b * 5 + 0];
        float ncy = cy + fin_s[b * 5 + 1];
        float nw = wd * __expf(fin_s[b * 5 + 2]);
        float nh = hg * __expf(fin_s[b * 5 + 3]);
        float conf = __fdividef(1.0f, 1.0f + __expf(-fin_s[b * 5 + 4]));
        float* op = p.out + (box0 + b) * 5;
        op[0] = ncx - nw * 0.5f;
        op[1] = ncy - nh * 0.5f;
        op[2] = ncx + nw * 0.5f;
        op[3] = ncy + nh * 0.5f;
        op[4] = conf;
    }
}

extern "C" void kernel_launch(void* const* d_in, const int* in_sizes, int n_in,
                              void* d_out, int out_size) {
    (void)in_sizes; (void)n_in; (void)out_size;
    Params p;
    p.mv       = (const float*)d_in[0];
    p.boxes    = (const float*)d_in[1];
    p.W_stats  = (const float*)d_in[2];
    p.b_stats  = (const float*)d_in[3];
    p.g_stats  = (const float*)d_in[4];
    p.be_stats = (const float*)d_in[5];
    p.W_b1     = (const float*)d_in[6];
    p.b_b1     = (const float*)d_in[7];
    p.g_b1     = (const float*)d_in[8];
    p.be_b1    = (const float*)d_in[9];
    p.W_b2     = (const float*)d_in[10];
    p.b_b2     = (const float*)d_in[11];
    p.g_b2     = (const float*)d_in[12];
    p.be_b2    = (const float*)d_in[13];
    p.W_ih     = (const float*)d_in[14];
    p.W_hh     = (const float*)d_in[15];
    p.b_ih     = (const float*)d_in[16];
    p.b_hh     = (const float*)d_in[17];
    p.W_p1     = (const float*)d_in[18];
    p.b_p1     = (const float*)d_in[19];
    p.W_p2     = (const float*)d_in[20];
    p.b_p2     = (const float*)d_in[21];
    p.W_s1     = (const float*)d_in[22];
    p.b_s1     = (const float*)d_in[23];
    p.W_s2     = (const float*)d_in[24];
    p.b_s2     = (const float*)d_in[25];
    p.W_c1     = (const float*)d_in[26];
    p.b_c1     = (const float*)d_in[27];
    p.W_c2     = (const float*)d_in[28];
    p.b_c2     = (const float*)d_in[29];
    p.out      = (float*)d_out;

    cudaFuncSetAttribute(tracker_fused_kernel,
                         cudaFuncAttributeMaxDynamicSharedMemorySize, SMEM_BYTES);
    tracker_fused_kernel<<<128, NT, SMEM_BYTES>>>(p);
}

// round 15
// speedup vs baseline: 1.1000x; 1.1000x over previous
#include <cuda_runtime.h>
#include <math.h>
#include <stdint.h>

#define GD 60
#define GG 3600
#define NT 1024

// device scratch: pre-converted tf32 weights (packed) + combined biases
__device__ uint32_t g_Wg[384 * 96];    // gates W, packed cols, k-pair-permuted
__device__ uint32_t g_Wh[192 * 128];   // heads W, k-pair-permuted
__device__ float    g_bias[384];       // [i(128) | g(128) | o(128)] = b_ih + b_hh

// shared memory layout (floats):
//   x_s  @ 0     : 32*104 = 3328   (tf32 bits, k-permuted)
//   wbuf @ 3328  : 384*104 = 39936 (gates W tf32; heads W 192*136=26112 + scr 6144 fit)
//   h_s  @ 43264 : 32*136 = 4352   (tf32 bits, k-permuted; phase-A hwarp overlays)
//   hid  @ 47616 : 32*196 = 6272
//   fin  @ 53888 : 160
#define XS_OFF   0
#define WB_OFF   3328
#define SCR_OFF  (WB_OFF + 26112)
#define HS_OFF   43264
#define HID_OFF  47616
#define FIN_OFF  53888
#define SMEM_FLOATS 54048
#define SMEM_BYTES (SMEM_FLOATS * 4)

struct Params {
    const float* mv;
    const float* boxes;
    const float* W_stats; const float* b_stats; const float* g_stats; const float* be_stats;
    const float* W_b1;    const float* b_b1;    const float* g_b1;    const float* be_b1;
    const float* W_b2;    const float* b_b2;    const float* g_b2;    const float* be_b2;
    const float* W_ih;    const float* W_hh;    const float* b_ih;    const float* b_hh;
    const float* W_p1;    const float* b_p1;    const float* W_p2;    const float* b_p2;
    const float* W_s1;    const float* b_s1;    const float* W_s2;    const float* b_s2;
    const float* W_c1;    const float* b_c1;    const float* W_c2;    const float* b_c2;
    float* out;
};

__device__ __forceinline__ float tanhfast(float x) {
    float y;
    asm("tanh.approx.f32 %0, %1;" : "=f"(y) : "f"(x));
    return y;
}
__device__ __forceinline__ float sigfast(float x) {
    return fmaf(0.5f, tanhfast(0.5f * x), 0.5f);
}
__device__ __forceinline__ uint32_t tf32cvt(float x) {
    uint32_t r;
    asm("cvt.rna.tf32.f32 %0, %1;" : "=r"(r) : "f"(x));
    return r;
}
// within each 8-k block: k<4 -> 2k ; k>=4 -> 2(k-4)+1   (pairs (k,k+4) adjacent)
__device__ __forceinline__ int permk(int c) {
    return (c & ~7) | ((c & 3) << 1) | ((c & 4) >> 2);
}
__device__ __forceinline__ void mma_tf32(float* d,
                                         uint32_t a0, uint32_t a1, uint32_t a2, uint32_t a3,
                                         uint32_t b0, uint32_t b1) {
    asm volatile(
        "mma.sync.aligned.m16n8k8.row.col.f32.tf32.tf32.f32 "
        "{%0,%1,%2,%3}, {%4,%5,%6,%7}, {%8,%9}, {%0,%1,%2,%3};"
        : "+f"(d[0]), "+f"(d[1]), "+f"(d[2]), "+f"(d[3])
        : "r"(a0), "r"(a1), "r"(a2), "r"(a3), "r"(b0), "r"(b1));
}
__device__ __forceinline__ void cp16(void* dst, const void* src) {
    unsigned saddr = (unsigned)__cvta_generic_to_shared(dst);
    asm volatile("cp.async.cg.shared.global [%0], [%1], 16;" :: "r"(saddr), "l"(src));
}

// ===========================================================================
// Prep kernel (unchanged from R10): convert + pack weights to tf32.
// ===========================================================================
__global__ void __launch_bounds__(256)
prep_kernel(Params p) {
    int tid = blockIdx.x * blockDim.x + threadIdx.x;
    int stride = gridDim.x * blockDim.x;
    for (int idx = tid; idx < 384 * 96; idx += stride) {
        int c = idx / 96, k = idx % 96;
        int ng = c / 48, cl = c % 48;
        int j = cl >> 3, r = cl & 7;
        int gate = j % 3;
        int u = 16 * ng + 8 * (j / 3) + r;
        int row = (gate == 0) ? u : (gate == 1) ? 256 + u : 384 + u;
        g_Wg[c * 96 + permk(k)] = tf32cvt(__ldg(p.W_ih + row * 96 + k));
    }
    for (int idx = tid; idx < 192 * 128; idx += stride) {
        int n = idx >> 7, k = idx & 127;
        const float* src = (n < 64) ? (p.W_p1 + n * 128)
                         : (n < 128) ? (p.W_s1 + (n - 64) * 128)
                                     : (p.W_c1 + (n - 128) * 128);
        g_Wh[n * 128 + permk(k)] = tf32cvt(__ldg(src + k));
    }
    if (tid < 384) {
        int t = tid >> 7, u = tid & 127;
        int row = (t == 0) ? u : (t == 1) ? 256 + u : 384 + u;
        g_bias[tid] = __ldg(p.b_ih + row) + __ldg(p.b_hh + row);
    }
}

// ===========================================================================
// Main fused kernel: 1024 threads, 32 warps
// ===========================================================================
__global__ void __launch_bounds__(NT, 1)
tracker_fused_kernel(Params p) {
    extern __shared__ float smem[];
    uint32_t* x_u    = (uint32_t*)(smem + XS_OFF);
    float*    wbuf   = smem + WB_OFF;
    uint32_t* wbuf_u = (uint32_t*)wbuf;
    float*    scr    = smem + SCR_OFF;     // 6144 floats (heads k-split partials)
    uint32_t* h_u    = (uint32_t*)(smem + HS_OFF);
    float*    hwarp  = smem + HS_OFF;      // phase-A overlay (1024 floats)
    float*    hid_s  = smem + HID_OFF;
    float*    fin_s  = smem + FIN_OFF;

    const int tid  = threadIdx.x;
    const int lane = tid & 31;
    const int w    = tid >> 5;        // 0..31
    const int gid  = lane >> 2;       // 0..7
    const int tig  = lane & 3;        // 0..3
    const int box0 = blockIdx.x * 32;

    // ---- stage gates W (tf32 + packed): 9216 float4, 9 per thread ----
    #pragma unroll
    for (int it = 0; it < 9; it++) {
        int idx = tid + it * NT;
        int n = idx / 24, k4 = idx % 24;
        cp16(wbuf_u + n * 104 + 4 * k4, g_Wg + n * 96 + 4 * k4);
    }
    asm volatile("cp.async.commit_group;");

    // ============ Phase A: one box per warp (box b = w) ============
    {
        const int b = w;
        float4 bxr = __ldg((const float4*)p.boxes + (box0 + b));
        float bn0 = fminf(fmaxf(bxr.x * (1.0f / 960.0f), 0.0f), 1.0f);
        float bn1 = fminf(fmaxf(bxr.y * (1.0f / 960.0f), 0.0f), 1.0f);
        float bn2 = fminf(fmaxf(bxr.z * (1.0f / 960.0f), 0.0f), 1.0f);
        float bn3 = fminf(fmaxf(bxr.w * (1.0f / 960.0f), 0.0f), 1.0f);

        int x1 = min(max((int)floorf(bn0 * 60.0f), 0), GD - 1);
        int y1 = min(max((int)floorf(bn1 * 60.0f), 0), GD - 1);
        int x2 = min(max((int)ceilf(bn2 * 60.0f), x1 + 1), GD);
        int y2 = min(max((int)ceilf(bn3 * 60.0f), y1 + 1), GD);
        int wd = x2 - x1;
        int area = wd * (y2 - y1);

        float s0 = 0.f, s1 = 0.f, q0 = 0.f, q1 = 0.f;
        float mx0 = -1e30f, mx1 = -1e30f, mn0 = 1e30f, mn1 = 1e30f;
        for (int c = lane; c < area; c += 32) {
            int ry = c / wd;
            int idx = (y1 + ry) * GD + x1 + (c - ry * wd);
            float v0 = __ldg(p.mv + idx);
            float v1 = __ldg(p.mv + GG + idx);
            s0 += v0; q0 += v0 * v0; mx0 = fmaxf(mx0, v0); mn0 = fminf(mn0, v0);
            s1 += v1; q1 += v1 * v1; mx1 = fmaxf(mx1, v1); mn1 = fminf(mn1, v1);
        }
        #pragma unroll
        for (int o = 16; o; o >>= 1) {
            s0 += __shfl_xor_sync(0xffffffffu, s0, o);
            s1 += __shfl_xor_sync(0xffffffffu, s1, o);
            q0 += __shfl_xor_sync(0xffffffffu, q0, o);
            q1 += __shfl_xor_sync(0xffffffffu, q1, o);
            mx0 = fmaxf(mx0, __shfl_xor_sync(0xffffffffu, mx0, o));
            mx1 = fmaxf(mx1, __shfl_xor_sync(0xffffffffu, mx1, o));
            mn0 = fminf(mn0, __shfl_xor_sync(0xffffffffu, mn0, o));
            mn1 = fminf(mn1, __shfl_xor_sync(0xffffffffu, mn1, o));
        }
        float rc = __fdividef(1.0f, (float)area);
        float m0s = s0 * rc, m1s = s1 * rc;
        float st[6];
        st[0] = m0s;
        st[1] = m1s;
        st[2] = sqrtf(fmaxf(q0 * rc - m0s * m0s, 0.0f));
        st[3] = sqrtf(fmaxf(q1 * rc - m1s * m1s, 0.0f));
        st[4] = mx0 - mn0;
        st[5] = mx1 - mn1;

        // z_mv: cols lane, lane+32
        float za = __ldg(p.b_stats + lane);
        float zb = __ldg(p.b_stats + lane + 32);
        const float* wsa = p.W_stats + lane * 6;
        const float* wsb = p.W_stats + (lane + 32) * 6;
        #pragma unroll
        for (int k = 0; k < 6; k++) {
            za = fmaf(st[k], __ldg(wsa + k), za);
            zb = fmaf(st[k], __ldg(wsb + k), zb);
        }
        {
            float s = za + zb, q = za * za + zb * zb;
            #pragma unroll
            for (int o = 16; o; o >>= 1) {
                s += __shfl_xor_sync(0xffffffffu, s, o);
                q += __shfl_xor_sync(0xffffffffu, q, o);
            }
            float mu = s * (1.0f / 64.0f);
            float inv = rsqrtf(fmaxf(q * (1.0f / 64.0f) - mu * mu, 0.0f) + 1e-5f);
            x_u[b * 104 + permk(lane)] =
                tf32cvt(fmaxf(fmaf((za - mu) * inv, __ldg(p.g_stats + lane), __ldg(p.be_stats + lane)), 0.0f));
            x_u[b * 104 + permk(lane + 32)] =
                tf32cvt(fmaxf(fmaf((zb - mu) * inv, __ldg(p.g_stats + lane + 32), __ldg(p.be_stats + lane + 32)), 0.0f));
        }

        // box path: 4 -> 32 LN relu -> 32 LN relu
        float4 wb1v = __ldg((const float4*)(p.W_b1) + lane);
        float t = __ldg(p.b_b1 + lane);
        t = fmaf(bn0, wb1v.x, t);
        t = fmaf(bn1, wb1v.y, t);
        t = fmaf(bn2, wb1v.z, t);
        t = fmaf(bn3, wb1v.w, t);
        {
            float s = t, q = t * t;
            #pragma unroll
            for (int o = 16; o; o >>= 1) {
                s += __shfl_xor_sync(0xffffffffu, s, o);
                q += __shfl_xor_sync(0xffffffffu, q, o);
            }
            float mu = s * (1.0f / 32.0f);
            float inv = rsqrtf(fmaxf(q * (1.0f / 32.0f) - mu * mu, 0.0f) + 1e-5f);
            hwarp[b * 32 + lane] =
                fmaxf(fmaf((t - mu) * inv, __ldg(p.g_b1 + lane), __ldg(p.be_b1 + lane)), 0.0f);
        }
        __syncwarp();
        float ta = __ldg(p.b_b2 + lane), tb = 0.0f;
        const float* wb2 = p.W_b2 + lane * 32;
        #pragma unroll
        for (int k4 = 0; k4 < 8; k4 += 2) {
            float4 wva = __ldg((const float4*)wb2 + k4);
            float4 wvb = __ldg((const float4*)wb2 + k4 + 1);
            const float* hp = hwarp + b * 32 + 4 * k4;
            ta = fmaf(hp[0], wva.x, ta);
            ta = fmaf(hp[1], wva.y, ta);
            ta = fmaf(hp[2], wva.z, ta);
            ta = fmaf(hp[3], wva.w, ta);
            tb = fmaf(hp[4], wvb.x, tb);
            tb = fmaf(hp[5], wvb.y, tb);
            tb = fmaf(hp[6], wvb.z, tb);
            tb = fmaf(hp[7], wvb.w, tb);
        }
        __syncwarp();
        {
            float t2 = ta + tb;
            float s = t2, q = t2 * t2;
            #pragma unroll
            for (int o = 16; o; o >>= 1) {
                s += __shfl_xor_sync(0xffffffffu, s, o);
                q += __shfl_xor_sync(0xffffffffu, q, o);
            }
            float mu = s * (1.0f / 32.0f);
            float inv = rsqrtf(fmaxf(q * (1.0f / 32.0f) - mu * mu, 0.0f) + 1e-5f);
            x_u[b * 104 + permk(64 + lane)] =
                tf32cvt(fmaxf(fmaf((t2 - mu) * inv, __ldg(p.g_b2 + lane), __ldg(p.be_b2 + lane)), 0.0f));
        }
    }

    asm volatile("cp.async.wait_group 0;");
    __syncthreads();   // x_u complete + gates W staged

    // ============ Gates GEMM via tf32 mma: 32 warps ============
    // mt = w&1 (M-tile of 16 boxes), ng = w>>1 (0..15): 24 packed cols = 8 units x (i,g,o)
    const int mt = w & 1;
    const int ng = w >> 1;
    const int m0 = mt * 16;

    float dacc[3][4];
    #pragma unroll
    for (int j = 0; j < 3; j++)
        #pragma unroll
        for (int q = 0; q < 4; q++) dacc[j][q] = 0.0f;

    #pragma unroll
    for (int ks = 0; ks < 12; ks++) {
        int k0 = 8 * ks;
        uint2 aA = *(const uint2*)(x_u + (m0 + gid) * 104 + k0 + 2 * tig);      // (a0,a2)
        uint2 aB = *(const uint2*)(x_u + (m0 + gid + 8) * 104 + k0 + 2 * tig);  // (a1,a3)
        #pragma unroll
        for (int j = 0; j < 3; j++) {
            int n = ng * 24 + 8 * j + gid;
            uint2 bv = *(const uint2*)(wbuf_u + n * 104 + k0 + 2 * tig);        // (b0,b1)
            mma_tf32(dacc[j], aA.x, aB.x, aA.y, aB.y, bv.x, bv.y);
        }
    }
    __syncthreads();   // gates-W reads done -> wbuf reusable

    // ---- stage heads W (tf32, permuted): 6144 float4, 6 per thread ----
    #pragma unroll
    for (int it = 0; it < 6; it++) {
        int idx = tid + it * NT;
        int n = idx >> 5, k4 = idx & 31;
        cp16(wbuf_u + n * 136 + 4 * k4, g_Wh + n * 128 + 4 * k4);
    }
    asm volatile("cp.async.commit_group;");

    // ============ LSTM fully in registers -> h_u (tf32, permuted) ============
    // j = 0,1,2 -> i,g,o of unit u = 16*(ng>>1) + 8*(ng&1) + 2*tig + e
    #pragma unroll
    for (int e = 0; e < 2; e++) {
        int u = 16 * (ng >> 1) + 8 * (ng & 1) + 2 * tig + e;
        float bi = __ldg(g_bias + u);
        float bg = __ldg(g_bias + 128 + u);
        float bo = __ldg(g_bias + 256 + u);
        {
            float iv = dacc[0][e] + bi;
            float gv = dacc[1][e] + bg;
            float ov = dacc[2][e] + bo;
            float c = sigfast(iv) * tanhfast(gv);
            h_u[(m0 + gid) * 136 + permk(u)] = tf32cvt(sigfast(ov) * tanhfast(c));
        }
        {
            float iv = dacc[0][2 + e] + bi;
            float gv = dacc[1][2 + e] + bg;
            float ov = dacc[2][2 + e] + bo;
            float c = sigfast(iv) * tanhfast(gv);
            h_u[(m0 + gid + 8) * 136 + permk(u)] = tf32cvt(sigfast(ov) * tanhfast(c));
        }
    }

    asm volatile("cp.async.wait_group 0;");
    __syncthreads();   // h complete + heads W staged

    // ============ Heads GEMM via tf32 mma: 32 warps, k-split in half ============
    // kh = w>>4 (k half), rem = w&15: mt2 = rem&1, cg = rem>>1 (0..7): 24 cols
    const int kh  = w >> 4;
    const int rem = w & 15;
    const int mt2 = rem & 1;
    const int cg  = rem >> 1;
    const int m02 = mt2 * 16;

    float hacc[3][4];
    #pragma unroll
    for (int j = 0; j < 3; j++)
        #pragma unroll
        for (int q = 0; q < 4; q++) hacc[j][q] = 0.0f;

    #pragma unroll
    for (int kk = 0; kk < 8; kk++) {
        int k0 = kh * 64 + 8 * kk;
        uint2 aA = *(const uint2*)(h_u + (m02 + gid) * 136 + k0 + 2 * tig);
        uint2 aB = *(const uint2*)(h_u + (m02 + gid + 8) * 136 + k0 + 2 * tig);
        #pragma unroll
        for (int j = 0; j < 3; j++) {
            int n = cg * 24 + 8 * j + gid;
            uint2 bv = *(const uint2*)(wbuf_u + n * 136 + k0 + 2 * tig);
            mma_tf32(hacc[j], aA.x, aB.x, aA.y, aB.y, bv.x, bv.y);
        }
    }

    // k-split combine through scr
    float* sq = scr + ((cg * 2 + mt2) * 32 + lane) * 12;
    if (kh == 1) {
        #pragma unroll
        for (int j = 0; j < 3; j++)
            #pragma unroll
            for (int q = 0; q < 4; q++) sq[j * 4 + q] = hacc[j][q];
    }
    __syncthreads();
    if (kh == 0) {
        #pragma unroll
        for (int j = 0; j < 3; j++) {
            int nc = cg * 24 + 8 * j + 2 * tig;
            float bias0 = (nc < 64) ? __ldg(p.b_p1 + nc)
                        : (nc < 128) ? __ldg(p.b_s1 + nc - 64)
                                     : __ldg(p.b_c1 + nc - 128);
            int nc1 = nc + 1;
            float bias1 = (nc1 < 64) ? __ldg(p.b_p1 + nc1)
                        : (nc1 < 128) ? __ldg(p.b_s1 + nc1 - 64)
                                      : __ldg(p.b_c1 + nc1 - 128);
            *(float2*)(hid_s + (m02 + gid) * 196 + nc) =
                make_float2(fmaxf(hacc[j][0] + sq[j * 4 + 0] + bias0, 0.0f),
                            fmaxf(hacc[j][1] + sq[j * 4 + 1] + bias1, 0.0f));
            *(float2*)(hid_s + (m02 + gid + 8) * 196 + nc) =
                make_float2(fmaxf(hacc[j][2] + sq[j * 4 + 2] + bias0, 0.0f),
                            fmaxf(hacc[j][3] + sq[j * 4 + 3] + bias1, 0.0f));
        }
    }
    __syncthreads();

    // ============ Head second layers (5 scalars per box) ============
    if (tid < 160) {
        int b = tid / 5, o = tid % 5;
        const float* hp = hid_s + b * 196 + ((o < 2) ? 0 : (o < 4) ? 64 : 128);
        const float* wp;
        float a;
        if (o == 0)      { wp = p.W_p2;      a = __ldg(p.b_p2); }
        else if (o == 1) { wp = p.W_p2 + 64; a = __ldg(p.b_p2 + 1); }
        else if (o == 2) { wp = p.W_s2;      a = __ldg(p.b_s2); }
        else if (o == 3) { wp = p.W_s2 + 64; a = __ldg(p.b_s2 + 1); }
        else             { wp = p.W_c2;      a = __ldg(p.b_c2); }
        #pragma unroll
        for (int k4 = 0; k4 < 16; k4++) {
            float4 hv = *(const float4*)(hp + 4 * k4);
            float4 wv = __ldg((const float4*)wp + k4);
            a = fmaf(hv.x, wv.x, a);
            a = fmaf(hv.y, wv.y, a);
            a = fmaf(hv.z, wv.z, a);
            a = fmaf(hv.w, wv.w, a);
        }
        fin_s[b * 5 + o] = a;
    }
    __syncthreads();

    // ============ Decode + output ============
    if (tid < 32) {
        int b = tid;
        float4 bx = __ldg((const float4*)p.boxes + (box0 + b));
        float cx = (bx.x + bx.z) * 0.5f, cy = (bx.y + bx.w) * 0.5f;
        float wd = bx.z - bx.x, hg = bx.w - bx.y;
        float ncx = cx + fin_s[b * 5 + 0];
        float ncy = cy + fin_s[b * 5 + 1];
        float nw = wd * __expf(fin_s[b * 5 + 2]);
        float nh = hg * __expf(fin_s[b * 5 + 3]);
        float conf = __fdividef(1.0f, 1.0f + __expf(-fin_s[b * 5 + 4]));
        float* op = p.out + (box0 + b) * 5;
        op[0] = ncx - nw * 0.5f;
        op[1] = ncy - nh * 0.5f;
        op[2] = ncx + nw * 0.5f;
        op[3] = ncy + nh * 0.5f;
        op[4] = conf;
    }
}

extern "C" void kernel_launch(void* const* d_in, const int* in_sizes, int n_in,
                              void* d_out, int out_size) {
    (void)in_sizes; (void)n_in; (void)out_size;
    Params p;
    p.mv       = (const float*)d_in[0];
    p.boxes    = (const float*)d_in[1];
    p.W_stats  = (const float*)d_in[2];
    p.b_stats  = (const float*)d_in[3];
    p.g_stats  = (const float*)d_in[4];
    p.be_stats = (const float*)d_in[5];
    p.W_b1     = (const float*)d_in[6];
    p.b_b1     = (const float*)d_in[7];
    p.g_b1     = (const float*)d_in[8];
    p.be_b1    = (const float*)d_in[9];
    p.W_b2     = (const float*)d_in[10];
    p.b_b2     = (const float*)d_in[11];
    p.g_b2     = (const float*)d_in[12];
    p.be_b2    = (const float*)d_in[13];
    p.W_ih     = (const float*)d_in[14];
    p.W_hh     = (const float*)d_in[15];
    p.b_ih     = (const float*)d_in[16];
    p.b_hh     = (const float*)d_in[17];
    p.W_p1     = (const float*)d_in[18];
    p.b_p1     = (const float*)d_in[19];
    p.W_p2     = (const float*)d_in[20];
    p.b_p2     = (const float*)d_in[21];
    p.W_s1     = (const float*)d_in[22];
    p.b_s1     = (const float*)d_in[23];
    p.W_s2     = (const float*)d_in[24];
    p.b_s2     = (const float*)d_in[25];
    p.W_c1     = (const float*)d_in[26];
    p.b_c1     = (const float*)d_in[27];
    p.W_c2     = (const float*)d_in[28];
    p.b_c2     = (const float*)d_in[29];
    p.out      = (float*)d_out;

    prep_kernel<<<128, 256>>>(p);
    cudaFuncSetAttribute(tracker_fused_kernel,
                         cudaFuncAttributeMaxDynamicSharedMemorySize, SMEM_BYTES);
    tracker_fused_kernel<<<128, NT, SMEM_BYTES>>>(p);
}

// round 16
// speedup vs baseline: 1.1699x; 1.0635x over previous
#include <cuda_runtime.h>
#include <cuda_bf16.h>
#include <math.h>
#include <stdint.h>

#define GD 60
#define GG 3600
#define NT 512

// device scratch: pre-converted bf16-packed weights + combined biases
__device__ uint32_t g_Wg[384 * 48];    // gates W, packed cols, bf16 pairs, u32-permuted
__device__ uint32_t g_Wh[192 * 64];    // heads W, bf16 pairs, u32-permuted
__device__ float    g_bias[384];       // [i(128) | g(128) | o(128)] = b_ih + b_hh

// shared memory layout (u32 units):
//   x_u  @ 0     : 32*52  = 1664   (bf16 pairs, permuted; 48 data + 4 pad)
//   wg   @ 1664  : 384*52 = 19968
//   wh   @ 21632 : 192*68 = 13056  (64 data + 4 pad)
//   h_u  @ 34688 : 32*68  = 2176   (phase-A hwarp float overlay: 1024)
//   hid  @ 36864 : 32*196 = 6272   (fp32)
//   fin  @ 43136 : 160
#define XS_OFF   0
#define WG_OFF   1664
#define WH_OFF   21632
#define HS_OFF   34688
#define HID_OFF  36864
#define FIN_OFF  43136
#define SMEM_U32 43296
#define SMEM_BYTES (SMEM_U32 * 4)

struct Params {
    const float* mv;
    const float* boxes;
    const float* W_stats; const float* b_stats; const float* g_stats; const float* be_stats;
    const float* W_b1;    const float* b_b1;    const float* g_b1;    const float* be_b1;
    const float* W_b2;    const float* b_b2;    const float* g_b2;    const float* be_b2;
    const float* W_ih;    const float* W_hh;    const float* b_ih;    const float* b_hh;
    const float* W_p1;    const float* b_p1;    const float* W_p2;    const float* b_p2;
    const float* W_s1;    const float* b_s1;    const float* W_s2;    const float* b_s2;
    const float* W_c1;    const float* b_c1;    const float* W_c2;    const float* b_c2;
    float* out;
};

__device__ __forceinline__ float tanhfast(float x) {
    float y;
    asm("tanh.approx.f32 %0, %1;" : "=f"(y) : "f"(x));
    return y;
}
__device__ __forceinline__ float sigfast(float x) {
    return fmaf(0.5f, tanhfast(0.5f * x), 0.5f);
}
__device__ __forceinline__ unsigned short bf16b(float x) {
    unsigned short r;
    asm("cvt.rn.bf16.f32 %0, %1;" : "=h"(r) : "f"(x));
    return r;
}
__device__ __forceinline__ uint32_t bf16pack(float lo, float hi) {
    return (uint32_t)bf16b(lo) | ((uint32_t)bf16b(hi) << 16);
}
// u32-level permutation within each 8-u32 (k16) block: j<4 -> 2j ; j>=4 -> 2(j-4)+1
__device__ __forceinline__ int pk(int j) {
    return (j & ~7) | ((j & 3) << 1) | ((j & 4) >> 2);
}
__device__ __forceinline__ void mma_bf16(float* d,
                                         uint32_t a0, uint32_t a1, uint32_t a2, uint32_t a3,
                                         uint32_t b0, uint32_t b1) {
    asm volatile(
        "mma.sync.aligned.m16n8k16.row.col.f32.bf16.bf16.f32 "
        "{%0,%1,%2,%3}, {%4,%5,%6,%7}, {%8,%9}, {%0,%1,%2,%3};"
        : "+f"(d[0]), "+f"(d[1]), "+f"(d[2]), "+f"(d[3])
        : "r"(a0), "r"(a1), "r"(a2), "r"(a3), "r"(b0), "r"(b1));
}
__device__ __forceinline__ void cp16(void* dst, const void* src) {
    unsigned saddr = (unsigned)__cvta_generic_to_shared(dst);
    asm volatile("cp.async.cg.shared.global [%0], [%1], 16;" :: "r"(saddr), "l"(src));
}
// packed gates col c -> original W_ih row (f skipped, (i,g,o) interleaved per 8-unit group)
__device__ __forceinline__ int gates_row(int c) {
    int ng = c / 48, cl = c % 48;
    int j = cl >> 3, r = cl & 7;
    int gate = j % 3;
    int u = 16 * ng + 8 * (j / 3) + r;
    return (gate == 0) ? u : (gate == 1) ? 256 + u : 384 + u;
}

// ===========================================================================
// Prep kernel: convert + pack weights to bf16 pairs once per launch.
// ===========================================================================
__global__ void __launch_bounds__(256)
prep_kernel(Params p) {
    int tid = blockIdx.x * blockDim.x + threadIdx.x;
    int stride = gridDim.x * blockDim.x;
    for (int idx = tid; idx < 384 * 48; idx += stride) {
        int c = idx / 48, j = idx % 48;
        int row = gates_row(c);
        float w0 = __ldg(p.W_ih + row * 96 + 2 * j);
        float w1 = __ldg(p.W_ih + row * 96 + 2 * j + 1);
        g_Wg[c * 48 + pk(j)] = bf16pack(w0, w1);
    }
    for (int idx = tid; idx < 192 * 64; idx += stride) {
        int n = idx >> 6, j = idx & 63;
        const float* src = (n < 64) ? (p.W_p1 + n * 128)
                         : (n < 128) ? (p.W_s1 + (n - 64) * 128)
                                     : (p.W_c1 + (n - 128) * 128);
        g_Wh[n * 64 + pk(j)] = bf16pack(__ldg(src + 2 * j), __ldg(src + 2 * j + 1));
    }
    if (tid < 384) {
        int t = tid >> 7, u = tid & 127;
        int row = (t == 0) ? u : (t == 1) ? 256 + u : 384 + u;
        g_bias[tid] = __ldg(p.b_ih + row) + __ldg(p.b_hh + row);
    }
}

// ===========================================================================
// Main fused kernel
// ===========================================================================
__global__ void __launch_bounds__(NT, 1)
tracker_fused_kernel(Params p) {
    extern __shared__ uint32_t smem[];
    uint32_t* x_u   = smem + XS_OFF;
    __nv_bfloat16* x_h = (__nv_bfloat16*)x_u;
    uint32_t* wg_u  = smem + WG_OFF;
    uint32_t* wh_u  = smem + WH_OFF;
    uint32_t* h_u   = smem + HS_OFF;
    float*    hwarp = (float*)(smem + HS_OFF);   // phase-A overlay (1024 floats)
    float*    hid_s = (float*)(smem + HID_OFF);
    float*    fin_s = (float*)(smem + FIN_OFF);

    const int tid  = threadIdx.x;
    const int lane = tid & 31;
    const int w    = tid >> 5;        // 0..15
    const int gid  = lane >> 2;       // 0..7
    const int tig  = lane & 3;        // 0..3
    const int box0 = blockIdx.x * 32;

    // ---- stage BOTH weight tiles in one group ----
    // gates: 384 rows x 12 float4 = 4608 ; heads: 192 x 16 = 3072
    #pragma unroll
    for (int it = 0; it < 9; it++) {
        int idx = tid + it * NT;
        int c = idx / 12, k4 = idx % 12;
        cp16(wg_u + c * 52 + 4 * k4, g_Wg + c * 48 + 4 * k4);
    }
    #pragma unroll
    for (int it = 0; it < 6; it++) {
        int idx = tid + it * NT;
        int n = idx >> 4, k4 = idx & 15;
        cp16(wh_u + n * 68 + 4 * k4, g_Wh + n * 64 + 4 * k4);
    }
    asm volatile("cp.async.commit_group;");

    // ============ Phase A: boxes 2w, 2w+1 interleaved -> x (bf16, permuted) ============
    {
        const int b0 = 2 * w, b1 = 2 * w + 1;

        const float* wsaP = p.W_stats + lane * 6;
        const float* wsbP = p.W_stats + (lane + 32) * 6;
        float ws_a[6], ws_b[6];
        #pragma unroll
        for (int k = 0; k < 6; k++) { ws_a[k] = __ldg(wsaP + k); ws_b[k] = __ldg(wsbP + k); }
        float bs_a  = __ldg(p.b_stats + lane),  bs_b  = __ldg(p.b_stats + lane + 32);
        float gs_a  = __ldg(p.g_stats + lane),  gs_b  = __ldg(p.g_stats + lane + 32);
        float bes_a = __ldg(p.be_stats + lane), bes_b = __ldg(p.be_stats + lane + 32);
        float4 wb1v = __ldg((const float4*)(p.W_b1) + lane);
        float bb1 = __ldg(p.b_b1 + lane), gb1 = __ldg(p.g_b1 + lane), beb1 = __ldg(p.be_b1 + lane);
        float bb2 = __ldg(p.b_b2 + lane), gb2 = __ldg(p.g_b2 + lane), beb2 = __ldg(p.be_b2 + lane);

        float4 bxA = __ldg((const float4*)p.boxes + (box0 + b0));
        float4 bxB = __ldg((const float4*)p.boxes + (box0 + b1));
        float anA0 = fminf(fmaxf(bxA.x * (1.0f / 960.0f), 0.0f), 1.0f);
        float anA1 = fminf(fmaxf(bxA.y * (1.0f / 960.0f), 0.0f), 1.0f);
        float anA2 = fminf(fmaxf(bxA.z * (1.0f / 960.0f), 0.0f), 1.0f);
        float anA3 = fminf(fmaxf(bxA.w * (1.0f / 960.0f), 0.0f), 1.0f);
        float anB0 = fminf(fmaxf(bxB.x * (1.0f / 960.0f), 0.0f), 1.0f);
        float anB1 = fminf(fmaxf(bxB.y * (1.0f / 960.0f), 0.0f), 1.0f);
        float anB2 = fminf(fmaxf(bxB.z * (1.0f / 960.0f), 0.0f), 1.0f);
        float anB3 = fminf(fmaxf(bxB.w * (1.0f / 960.0f), 0.0f), 1.0f);

        int xA1 = min(max((int)floorf(anA0 * 60.0f), 0), GD - 1);
        int yA1 = min(max((int)floorf(anA1 * 60.0f), 0), GD - 1);
        int xA2 = min(max((int)ceilf(anA2 * 60.0f), xA1 + 1), GD);
        int yA2 = min(max((int)ceilf(anA3 * 60.0f), yA1 + 1), GD);
        int xB1 = min(max((int)floorf(anB0 * 60.0f), 0), GD - 1);
        int yB1 = min(max((int)floorf(anB1 * 60.0f), 0), GD - 1);
        int xB2 = min(max((int)ceilf(anB2 * 60.0f), xB1 + 1), GD);
        int yB2 = min(max((int)ceilf(anB3 * 60.0f), yB1 + 1), GD);
        int wdA = xA2 - xA1, areaA = wdA * (yA2 - yA1);
        int wdB = xB2 - xB1, areaB = wdB * (yB2 - yB1);
        int maxArea = max(areaA, areaB);

        float sA0 = 0.f, sA1 = 0.f, qA0 = 0.f, qA1 = 0.f;
        float mxA0 = -1e30f, mxA1 = -1e30f, mnA0 = 1e30f, mnA1 = 1e30f;
        float sB0 = 0.f, sB1 = 0.f, qB0 = 0.f, qB1 = 0.f;
        float mxB0 = -1e30f, mxB1 = -1e30f, mnB0 = 1e30f, mnB1 = 1e30f;

        for (int c = lane; c < maxArea; c += 32) {
            if (c < areaA) {
                int ry = c / wdA;
                int idx = (yA1 + ry) * GD + xA1 + (c - ry * wdA);
                float v0 = __ldg(p.mv + idx);
                float v1 = __ldg(p.mv + GG + idx);
                sA0 += v0; qA0 += v0 * v0; mxA0 = fmaxf(mxA0, v0); mnA0 = fminf(mnA0, v0);
                sA1 += v1; qA1 += v1 * v1; mxA1 = fmaxf(mxA1, v1); mnA1 = fminf(mnA1, v1);
            }
            if (c < areaB) {
                int ry = c / wdB;
                int idx = (yB1 + ry) * GD + xB1 + (c - ry * wdB);
                float v0 = __ldg(p.mv + idx);
                float v1 = __ldg(p.mv + GG + idx);
                sB0 += v0; qB0 += v0 * v0; mxB0 = fmaxf(mxB0, v0); mnB0 = fminf(mnB0, v0);
                sB1 += v1; qB1 += v1 * v1; mxB1 = fmaxf(mxB1, v1); mnB1 = fminf(mnB1, v1);
            }
        }
        #pragma unroll
        for (int o = 16; o; o >>= 1) {
            sA0 += __shfl_xor_sync(0xffffffffu, sA0, o);
            sA1 += __shfl_xor_sync(0xffffffffu, sA1, o);
            qA0 += __shfl_xor_sync(0xffffffffu, qA0, o);
            qA1 += __shfl_xor_sync(0xffffffffu, qA1, o);
            sB0 += __shfl_xor_sync(0xffffffffu, sB0, o);
            sB1 += __shfl_xor_sync(0xffffffffu, sB1, o);
            qB0 += __shfl_xor_sync(0xffffffffu, qB0, o);
            qB1 += __shfl_xor_sync(0xffffffffu, qB1, o);
            mxA0 = fmaxf(mxA0, __shfl_xor_sync(0xffffffffu, mxA0, o));
            mxA1 = fmaxf(mxA1, __shfl_xor_sync(0xffffffffu, mxA1, o));
            mnA0 = fminf(mnA0, __shfl_xor_sync(0xffffffffu, mnA0, o));
            mnA1 = fminf(mnA1, __shfl_xor_sync(0xffffffffu, mnA1, o));
            mxB0 = fmaxf(mxB0, __shfl_xor_sync(0xffffffffu, mxB0, o));
            mxB1 = fmaxf(mxB1, __shfl_xor_sync(0xffffffffu, mxB1, o));
            mnB0 = fminf(mnB0, __shfl_xor_sync(0xffffffffu, mnB0, o));
            mnB1 = fminf(mnB1, __shfl_xor_sync(0xffffffffu, mnB1, o));
        }
        float rcA = __fdividef(1.0f, (float)areaA);
        float rcB = __fdividef(1.0f, (float)areaB);
        float mA0 = sA0 * rcA, mA1 = sA1 * rcA;
        float mB0 = sB0 * rcB, mB1 = sB1 * rcB;
        float stA[6], stB[6];
        stA[0] = mA0; stA[1] = mA1;
        stA[2] = sqrtf(fmaxf(qA0 * rcA - mA0 * mA0, 0.0f));
        stA[3] = sqrtf(fmaxf(qA1 * rcA - mA1 * mA1, 0.0f));
        stA[4] = mxA0 - mnA0; stA[5] = mxA1 - mnA1;
        stB[0] = mB0; stB[1] = mB1;
        stB[2] = sqrtf(fmaxf(qB0 * rcB - mB0 * mB0, 0.0f));
        stB[3] = sqrtf(fmaxf(qB1 * rcB - mB1 * mB1, 0.0f));
        stB[4] = mxB0 - mnB0; stB[5] = mxB1 - mnB1;

        float zAa = bs_a, zAb = bs_b, zBa = bs_a, zBb = bs_b;
        #pragma unroll
        for (int k = 0; k < 6; k++) {
            zAa = fmaf(stA[k], ws_a[k], zAa);
            zAb = fmaf(stA[k], ws_b[k], zAb);
            zBa = fmaf(stB[k], ws_a[k], zBa);
            zBb = fmaf(stB[k], ws_b[k], zBb);
        }
        {
            float sA = zAa + zAb, qA = zAa * zAa + zAb * zAb;
            float sB = zBa + zBb, qB = zBa * zBa + zBb * zBb;
            #pragma unroll
            for (int o = 16; o; o >>= 1) {
                sA += __shfl_xor_sync(0xffffffffu, sA, o);
                qA += __shfl_xor_sync(0xffffffffu, qA, o);
                sB += __shfl_xor_sync(0xffffffffu, sB, o);
                qB += __shfl_xor_sync(0xffffffffu, qB, o);
            }
            float muA = sA * (1.0f / 64.0f);
            float invA = rsqrtf(fmaxf(qA * (1.0f / 64.0f) - muA * muA, 0.0f) + 1e-5f);
            float muB = sB * (1.0f / 64.0f);
            float invB = rsqrtf(fmaxf(qB * (1.0f / 64.0f) - muB * muB, 0.0f) + 1e-5f);
            float vA0 = fmaxf(fmaf((zAa - muA) * invA, gs_a, bes_a), 0.0f);
            float vA1 = fmaxf(fmaf((zAb - muA) * invA, gs_b, bes_b), 0.0f);
            float vB0 = fmaxf(fmaf((zBa - muB) * invB, gs_a, bes_a), 0.0f);
            float vB1 = fmaxf(fmaf((zBb - muB) * invB, gs_b, bes_b), 0.0f);
            int c0 = lane, c1 = lane + 32;
            x_h[(b0 * 52 + pk(c0 >> 1)) * 2 + (c0 & 1)] = __ushort_as_bfloat16(bf16b(vA0));
            x_h[(b0 * 52 + pk(c1 >> 1)) * 2 + (c1 & 1)] = __ushort_as_bfloat16(bf16b(vA1));
            x_h[(b1 * 52 + pk(c0 >> 1)) * 2 + (c0 & 1)] = __ushort_as_bfloat16(bf16b(vB0));
            x_h[(b1 * 52 + pk(c1 >> 1)) * 2 + (c1 & 1)] = __ushort_as_bfloat16(bf16b(vB1));
        }

        float tA = bb1, tB = bb1;
        tA = fmaf(anA0, wb1v.x, tA); tB = fmaf(anB0, wb1v.x, tB);
        tA = fmaf(anA1, wb1v.y, tA); tB = fmaf(anB1, wb1v.y, tB);
        tA = fmaf(anA2, wb1v.z, tA); tB = fmaf(anB2, wb1v.z, tB);
        tA = fmaf(anA3, wb1v.w, tA); tB = fmaf(anB3, wb1v.w, tB);
        {
            float sA = tA, qA = tA * tA, sB = tB, qB = tB * tB;
            #pragma unroll
            for (int o = 16; o; o >>= 1) {
                sA += __shfl_xor_sync(0xffffffffu, sA, o);
                qA += __shfl_xor_sync(0xffffffffu, qA, o);
                sB += __shfl_xor_sync(0xffffffffu, sB, o);
                qB += __shfl_xor_sync(0xffffffffu, qB, o);
            }
            float muA = sA * (1.0f / 32.0f);
            float invA = rsqrtf(fmaxf(qA * (1.0f / 32.0f) - muA * muA, 0.0f) + 1e-5f);
            float muB = sB * (1.0f / 32.0f);
            float invB = rsqrtf(fmaxf(qB * (1.0f / 32.0f) - muB * muB, 0.0f) + 1e-5f);
            hwarp[b0 * 32 + lane] = fmaxf(fmaf((tA - muA) * invA, gb1, beb1), 0.0f);
            hwarp[b1 * 32 + lane] = fmaxf(fmaf((tB - muB) * invB, gb1, beb1), 0.0f);
        }
        __syncwarp();
        float tA0 = bb2, tA1 = 0.0f, tB0 = bb2, tB1 = 0.0f;
        const float* wb2 = p.W_b2 + lane * 32;
        #pragma unroll
        for (int k4 = 0; k4 < 8; k4 += 2) {
            float4 wva = __ldg((const float4*)wb2 + k4);
            float4 wvb = __ldg((const float4*)wb2 + k4 + 1);
            const float* hpA = hwarp + b0 * 32 + 4 * k4;
            const float* hpB = hwarp + b1 * 32 + 4 * k4;
            tA0 = fmaf(hpA[0], wva.x, tA0); tB0 = fmaf(hpB[0], wva.x, tB0);
            tA0 = fmaf(hpA[1], wva.y, tA0); tB0 = fmaf(hpB[1], wva.y, tB0);
            tA0 = fmaf(hpA[2], wva.z, tA0); tB0 = fmaf(hpB[2], wva.z, tB0);
            tA0 = fmaf(hpA[3], wva.w, tA0); tB0 = fmaf(hpB[3], wva.w, tB0);
            tA1 = fmaf(hpA[4], wvb.x, tA1); tB1 = fmaf(hpB[4], wvb.x, tB1);
            tA1 = fmaf(hpA[5], wvb.y, tA1); tB1 = fmaf(hpB[5], wvb.y, tB1);
            tA1 = fmaf(hpA[6], wvb.z, tA1); tB1 = fmaf(hpB[6], wvb.z, tB1);
            tA1 = fmaf(hpA[7], wvb.w, tA1); tB1 = fmaf(hpB[7], wvb.w, tB1);
        }
        __syncwarp();
        {
            float t2A = tA0 + tA1, t2B = tB0 + tB1;
            float sA = t2A, qA = t2A * t2A, sB = t2B, qB = t2B * t2B;
            #pragma unroll
            for (int o = 16; o; o >>= 1) {
                sA += __shfl_xor_sync(0xffffffffu, sA, o);
                qA += __shfl_xor_sync(0xffffffffu, qA, o);
                sB += __shfl_xor_sync(0xffffffffu, sB, o);
                qB += __shfl_xor_sync(0xffffffffu, qB, o);
            }
            float muA = sA * (1.0f / 32.0f);
            float invA = rsqrtf(fmaxf(qA * (1.0f / 32.0f) - muA * muA, 0.0f) + 1e-5f);
            float muB = sB * (1.0f / 32.0f);
            float invB = rsqrtf(fmaxf(qB * (1.0f / 32.0f) - muB * muB, 0.0f) + 1e-5f);
            float vA = fmaxf(fmaf((t2A - muA) * invA, gb2, beb2), 0.0f);
            float vB = fmaxf(fmaf((t2B - muB) * invB, gb2, beb2), 0.0f);
            int c2 = 64 + lane;
            x_h[(b0 * 52 + pk(c2 >> 1)) * 2 + (c2 & 1)] = __ushort_as_bfloat16(bf16b(vA));
            x_h[(b1 * 52 + pk(c2 >> 1)) * 2 + (c2 & 1)] = __ushort_as_bfloat16(bf16b(vB));
        }
    }

    asm volatile("cp.async.wait_group 0;");
    __syncthreads();   // x complete + both weight tiles staged

    // ============ Gates GEMM via bf16 mma (k16): 6 k-steps ============
    const int mt = w & 1;         // M-tile (16 boxes)
    const int ng = w >> 1;        // 0..7 : 48 packed cols = 16 units x (i,g,o)
    const int m0 = mt * 16;

    float dacc[6][4];
    #pragma unroll
    for (int j = 0; j < 6; j++)
        #pragma unroll
        for (int q = 0; q < 4; q++) dacc[j][q] = 0.0f;

    #pragma unroll
    for (int ks = 0; ks < 6; ks++) {
        int k0 = 8 * ks;
        uint2 aA = *(const uint2*)(x_u + (m0 + gid) * 52 + k0 + 2 * tig);      // (a0,a2)
        uint2 aB = *(const uint2*)(x_u + (m0 + gid + 8) * 52 + k0 + 2 * tig);  // (a1,a3)
        #pragma unroll
        for (int j = 0; j < 6; j++) {
            int n = ng * 48 + 8 * j + gid;
            uint2 bv = *(const uint2*)(wg_u + n * 52 + k0 + 2 * tig);          // (b0,b1)
            mma_bf16(dacc[j], aA.x, aB.x, aA.y, aB.y, bv.x, bv.y);
        }
    }

    // ============ LSTM fully in registers -> h (bf16 pairs, permuted) ============
    #pragma unroll
    for (int jj = 0; jj < 2; jj++) {
        int u0 = 16 * ng + 8 * jj + 2 * tig;     // even unit; partner u0+1
        int jp = pk(u0 >> 1);                    // u32 slot
        float bi0 = __ldg(g_bias + u0),       bi1 = __ldg(g_bias + u0 + 1);
        float bg0 = __ldg(g_bias + 128 + u0), bg1 = __ldg(g_bias + 128 + u0 + 1);
        float bo0 = __ldg(g_bias + 256 + u0), bo1 = __ldg(g_bias + 256 + u0 + 1);
        {
            float c0 = sigfast(dacc[3 * jj + 0][0] + bi0) * tanhfast(dacc[3 * jj + 1][0] + bg0);
            float h0 = sigfast(dacc[3 * jj + 2][0] + bo0) * tanhfast(c0);
            float c1 = sigfast(dacc[3 * jj + 0][1] + bi1) * tanhfast(dacc[3 * jj + 1][1] + bg1);
            float h1 = sigfast(dacc[3 * jj + 2][1] + bo1) * tanhfast(c1);
            h_u[(m0 + gid) * 68 + jp] = bf16pack(h0, h1);
        }
        {
            float c0 = sigfast(dacc[3 * jj + 0][2] + bi0) * tanhfast(dacc[3 * jj + 1][2] + bg0);
            float h0 = sigfast(dacc[3 * jj + 2][2] + bo0) * tanhfast(c0);
            float c1 = sigfast(dacc[3 * jj + 0][3] + bi1) * tanhfast(dacc[3 * jj + 1][3] + bg1);
            float h1 = sigfast(dacc[3 * jj + 2][3] + bo1) * tanhfast(c1);
            h_u[(m0 + gid + 8) * 68 + jp] = bf16pack(h0, h1);
        }
    }
    __syncthreads();   // h visible

    // ============ Heads GEMM via bf16 mma: 8 k-steps, full K ============
    // mt2 = w&1, cg = w>>1 (0..7): 24 cols each
    float hacc[3][4];
    #pragma unroll
    for (int j = 0; j < 3; j++)
        #pragma unroll
        for (int q = 0; q < 4; q++) hacc[j][q] = 0.0f;

    #pragma unroll
    for (int ks = 0; ks < 8; ks++) {
        int k0 = 8 * ks;
        uint2 aA = *(const uint2*)(h_u + (m0 + gid) * 68 + k0 + 2 * tig);
        uint2 aB = *(const uint2*)(h_u + (m0 + gid + 8) * 68 + k0 + 2 * tig);
        #pragma unroll
        for (int j = 0; j < 3; j++) {
            int n = ng * 24 + 8 * j + gid;
            uint2 bv = *(const uint2*)(wh_u + n * 68 + k0 + 2 * tig);
            mma_bf16(hacc[j], aA.x, aB.x, aA.y, aB.y, bv.x, bv.y);
        }
    }

    // ---- epilogue: bias + relu -> hid_s [32][196] ----
    #pragma unroll
    for (int j = 0; j < 3; j++) {
        int nc = ng * 24 + 8 * j + 2 * tig;
        float bias0 = (nc < 64) ? __ldg(p.b_p1 + nc)
                    : (nc < 128) ? __ldg(p.b_s1 + nc - 64)
                                 : __ldg(p.b_c1 + nc - 128);
        int nc1 = nc + 1;
        float bias1 = (nc1 < 64) ? __ldg(p.b_p1 + nc1)
                    : (nc1 < 128) ? __ldg(p.b_s1 + nc1 - 64)
                                  : __ldg(p.b_c1 + nc1 - 128);
        *(float2*)(hid_s + (m0 + gid) * 196 + nc) =
            make_float2(fmaxf(hacc[j][0] + bias0, 0.0f), fmaxf(hacc[j][1] + bias1, 0.0f));
        *(float2*)(hid_s + (m0 + gid + 8) * 196 + nc) =
            make_float2(fmaxf(hacc[j][2] + bias0, 0.0f), fmaxf(hacc[j][3] + bias1, 0.0f));
    }
    __syncthreads();

    // ============ Head second layers (5 scalars per box) ============
    if (tid < 160) {
        int b = tid / 5, o = tid % 5;
        const float* hp = hid_s + b * 196 + ((o < 2) ? 0 : (o < 4) ? 64 : 128);
        const float* wp;
        float a;
        if (o == 0)      { wp = p.W_p2;      a = __ldg(p.b_p2); }
        else if (o == 1) { wp = p.W_p2 + 64; a = __ldg(p.b_p2 + 1); }
        else if (o == 2) { wp = p.W_s2;      a = __ldg(p.b_s2); }
        else if (o == 3) { wp = p.W_s2 + 64; a = __ldg(p.b_s2 + 1); }
        else             { wp = p.W_c2;      a = __ldg(p.b_c2); }
        #pragma unroll
        for (int k4 = 0; k4 < 16; k4++) {
            float4 hv = *(const float4*)(hp + 4 * k4);
            float4 wv = __ldg((const float4*)wp + k4);
            a = fmaf(hv.x, wv.x, a);
            a = fmaf(hv.y, wv.y, a);
            a = fmaf(hv.z, wv.z, a);
            a = fmaf(hv.w, wv.w, a);
        }
        fin_s[b * 5 + o] = a;
    }
    __syncthreads();

    // ============ Decode + output ============
    if (tid < 32) {
        int b = tid;
        float4 bx = __ldg((const float4*)p.boxes + (box0 + b));
        float cx = (bx.x + bx.z) * 0.5f, cy = (bx.y + bx.w) * 0.5f;
        float wd = bx.z - bx.x, hg = bx.w - bx.y;
        float ncx = cx + fin_s[b * 5 + 0];
        float ncy = cy + fin_s[b * 5 + 1];
        float nw = wd * __expf(fin_s[b * 5 + 2]);
        float nh = hg * __expf(fin_s[b * 5 + 3]);
        float conf = __fdividef(1.0f, 1.0f + __expf(-fin_s[b * 5 + 4]));
        float* op = p.out + (box0 + b) * 5;
        op[0] = ncx - nw * 0.5f;
        op[1] = ncy - nh * 0.5f;
        op[2] = ncx + nw * 0.5f;
        op[3] = ncy + nh * 0.5f;
        op[4] = conf;
    }
}

extern "C" void kernel_launch(void* const* d_in, const int* in_sizes, int n_in,
                              void* d_out, int out_size) {
    (void)in_sizes; (void)n_in; (void)out_size;
    Params p;
    p.mv       = (const float*)d_in[0];
    p.boxes    = (const float*)d_in[1];
    p.W_stats  = (const float*)d_in[2];
    p.b_stats  = (const float*)d_in[3];
    p.g_stats  = (const float*)d_in[4];
    p.be_stats = (const float*)d_in[5];
    p.W_b1     = (const float*)d_in[6];
    p.b_b1     = (const float*)d_in[7];
    p.g_b1     = (const float*)d_in[8];
    p.be_b1    = (const float*)d_in[9];
    p.W_b2     = (const float*)d_in[10];
    p.b_b2     = (const float*)d_in[11];
    p.g_b2     = (const float*)d_in[12];
    p.be_b2    = (const float*)d_in[13];
    p.W_ih     = (const float*)d_in[14];
    p.W_hh     = (const float*)d_in[15];
    p.b_ih     = (const float*)d_in[16];
    p.b_hh     = (const float*)d_in[17];
    p.W_p1     = (const float*)d_in[18];
    p.b_p1     = (const float*)d_in[19];
    p.W_p2     = (const float*)d_in[20];
    p.b_p2     = (const float*)d_in[21];
    p.W_s1     = (const float*)d_in[22];
    p.b_s1     = (const float*)d_in[23];
    p.W_s2     = (const float*)d_in[24];
    p.b_s2     = (const float*)d_in[25];
    p.W_c1     = (const float*)d_in[26];
    p.b_c1     = (const float*)d_in[27];
    p.W_c2     = (const float*)d_in[28];
    p.b_c2     = (const float*)d_in[29];
    p.out      = (float*)d_out;

    prep_kernel<<<128, 256>>>(p);
    cudaFuncSetAttribute(tracker_fused_kernel,
                         cudaFuncAttributeMaxDynamicSharedMemorySize, SMEM_BYTES);
    tracker_fused_kernel<<<128, NT, SMEM_BYTES>>>(p);
}

// round 17
// speedup vs baseline: 1.2336x; 1.0545x over previous
#include <cuda_runtime.h>
#include <cuda_bf16.h>
#include <math.h>
#include <stdint.h>

#define GD 60
#define GG 3600
#define NT 512

// device scratch: pre-converted bf16-packed weights + combined biases
__device__ uint32_t g_Wg[384 * 48];    // gates W, packed cols, bf16 pairs, u32-permuted
__device__ uint32_t g_Wh[192 * 64];    // heads W, bf16 pairs, u32-permuted
__device__ uint32_t g_W2[8 * 96];      // head-2 W, zero-padded [8 x 192] bf16, u32-permuted
__device__ float    g_bias[384];       // [i(128) | g(128) | o(128)] = b_ih + b_hh

// shared memory layout (u32 units):
//   x_u  @ 0     : 32*52  = 1664
//   wg   @ 1664  : 384*52 = 19968
//   wh   @ 21632 : 192*68 = 13056
//   w2   @ 34688 : 8*100  = 800
//   h_u  @ 35488 : 32*68  = 2176   (phase-A hwarp float overlay: 1024)
//   hid  @ 37664 : 32*100 = 3200   (bf16 pairs, permuted)
//   fin  @ 40864 : 160
#define XS_OFF   0
#define WG_OFF   1664
#define WH_OFF   21632
#define W2_OFF   34688
#define HS_OFF   35488
#define HID_OFF  37664
#define FIN_OFF  40864
#define SMEM_U32 41024
#define SMEM_BYTES (SMEM_U32 * 4)

struct Params {
    const float* mv;
    const float* boxes;
    const float* W_stats; const float* b_stats; const float* g_stats; const float* be_stats;
    const float* W_b1;    const float* b_b1;    const float* g_b1;    const float* be_b1;
    const float* W_b2;    const float* b_b2;    const float* g_b2;    const float* be_b2;
    const float* W_ih;    const float* W_hh;    const float* b_ih;    const float* b_hh;
    const float* W_p1;    const float* b_p1;    const float* W_p2;    const float* b_p2;
    const float* W_s1;    const float* b_s1;    const float* W_s2;    const float* b_s2;
    const float* W_c1;    const float* b_c1;    const float* W_c2;    const float* b_c2;
    float* out;
};

__device__ __forceinline__ float tanhfast(float x) {
    float y;
    asm("tanh.approx.f32 %0, %1;" : "=f"(y) : "f"(x));
    return y;
}
__device__ __forceinline__ float sigfast(float x) {
    return fmaf(0.5f, tanhfast(0.5f * x), 0.5f);
}
__device__ __forceinline__ unsigned short bf16b(float x) {
    unsigned short r;
    asm("cvt.rn.bf16.f32 %0, %1;" : "=h"(r) : "f"(x));
    return r;
}
__device__ __forceinline__ uint32_t bf16pack(float lo, float hi) {
    return (uint32_t)bf16b(lo) | ((uint32_t)bf16b(hi) << 16);
}
// u32-level permutation within each 8-u32 (k16) block: j<4 -> 2j ; j>=4 -> 2(j-4)+1
__device__ __forceinline__ int pk(int j) {
    return (j & ~7) | ((j & 3) << 1) | ((j & 4) >> 2);
}
__device__ __forceinline__ void mma_bf16(float* d,
                                         uint32_t a0, uint32_t a1, uint32_t a2, uint32_t a3,
                                         uint32_t b0, uint32_t b1) {
    asm volatile(
        "mma.sync.aligned.m16n8k16.row.col.f32.bf16.bf16.f32 "
        "{%0,%1,%2,%3}, {%4,%5,%6,%7}, {%8,%9}, {%0,%1,%2,%3};"
        : "+f"(d[0]), "+f"(d[1]), "+f"(d[2]), "+f"(d[3])
        : "r"(a0), "r"(a1), "r"(a2), "r"(a3), "r"(b0), "r"(b1));
}
__device__ __forceinline__ void cp16(void* dst, const void* src) {
    unsigned saddr = (unsigned)__cvta_generic_to_shared(dst);
    asm volatile("cp.async.cg.shared.global [%0], [%1], 16;" :: "r"(saddr), "l"(src));
}
__device__ __forceinline__ int gates_row(int c) {
    int ng = c / 48, cl = c % 48;
    int j = cl >> 3, r = cl & 7;
    int gate = j % 3;
    int u = 16 * ng + 8 * (j / 3) + r;
    return (gate == 0) ? u : (gate == 1) ? 256 + u : 384 + u;
}

// ===========================================================================
// Prep kernel: convert + pack weights to bf16 pairs once per launch.
// ===========================================================================
__global__ void __launch_bounds__(256)
prep_kernel(Params p) {
    int tid = blockIdx.x * blockDim.x + threadIdx.x;
    int stride = gridDim.x * blockDim.x;
    for (int idx = tid; idx < 384 * 48; idx += stride) {
        int c = idx / 48, j = idx % 48;
        int row = gates_row(c);
        float w0 = __ldg(p.W_ih + row * 96 + 2 * j);
        float w1 = __ldg(p.W_ih + row * 96 + 2 * j + 1);
        g_Wg[c * 48 + pk(j)] = bf16pack(w0, w1);
    }
    for (int idx = tid; idx < 192 * 64; idx += stride) {
        int n = idx >> 6, j = idx & 63;
        const float* src = (n < 64) ? (p.W_p1 + n * 128)
                         : (n < 128) ? (p.W_s1 + (n - 64) * 128)
                                     : (p.W_c1 + (n - 128) * 128);
        g_Wh[n * 64 + pk(j)] = bf16pack(__ldg(src + 2 * j), __ldg(src + 2 * j + 1));
    }
    // head-2 W: [8 x 192] bf16 (96 u32/row), zero-padded block structure
    for (int idx = tid; idx < 8 * 96; idx += stride) {
        int n = idx / 96, j = idx % 96;  // k pair = (2j, 2j+1)
        float w0 = 0.0f, w1 = 0.0f;
        const float* src = nullptr;
        int koff = 0;
        if (n == 0)      { src = p.W_p2;      koff = 0; }
        else if (n == 1) { src = p.W_p2 + 64; koff = 0; }
        else if (n == 2) { src = p.W_s2;      koff = 64; }
        else if (n == 3) { src = p.W_s2 + 64; koff = 64; }
        else if (n == 4) { src = p.W_c2;      koff = 128; }
        int k = 2 * j;
        if (src && k >= koff && k < koff + 64) {
            w0 = __ldg(src + k - koff);
            w1 = __ldg(src + k + 1 - koff);
        }
        g_W2[n * 96 + pk(j)] = bf16pack(w0, w1);
    }
    if (tid < 384) {
        int t = tid >> 7, u = tid & 127;
        int row = (t == 0) ? u : (t == 1) ? 256 + u : 384 + u;
        g_bias[tid] = __ldg(p.b_ih + row) + __ldg(p.b_hh + row);
    }
}

// ===========================================================================
// Main fused kernel
// ===========================================================================
__global__ void __launch_bounds__(NT, 1)
tracker_fused_kernel(Params p) {
    extern __shared__ uint32_t smem[];
    uint32_t* x_u   = smem + XS_OFF;
    __nv_bfloat16* x_h = (__nv_bfloat16*)x_u;
    uint32_t* wg_u  = smem + WG_OFF;
    uint32_t* wh_u  = smem + WH_OFF;
    uint32_t* w2_u  = smem + W2_OFF;
    uint32_t* h_u   = smem + HS_OFF;
    float*    hwarp = (float*)(smem + HS_OFF);   // phase-A overlay
    uint32_t* hid_u = smem + HID_OFF;            // [32][100] bf16 pairs
    float*    fin_s = (float*)(smem + FIN_OFF);

    const int tid  = threadIdx.x;
    const int lane = tid & 31;
    const int w    = tid >> 5;        // 0..15
    const int gid  = lane >> 2;       // 0..7
    const int tig  = lane & 3;        // 0..3
    const int box0 = blockIdx.x * 32;

    // ---- stage ALL weight tiles in one group ----
    #pragma unroll
    for (int it = 0; it < 9; it++) {
        int idx = tid + it * NT;
        int c = idx / 12, k4 = idx % 12;
        cp16(wg_u + c * 52 + 4 * k4, g_Wg + c * 48 + 4 * k4);
    }
    #pragma unroll
    for (int it = 0; it < 6; it++) {
        int idx = tid + it * NT;
        int n = idx >> 4, k4 = idx & 15;
        cp16(wh_u + n * 68 + 4 * k4, g_Wh + n * 64 + 4 * k4);
    }
    if (tid < 192) {
        int n = tid / 24, k4 = tid % 24;
        cp16(w2_u + n * 100 + 4 * k4, g_W2 + n * 96 + 4 * k4);
    }
    asm volatile("cp.async.commit_group;");

    // ============ Phase A: boxes 2w, 2w+1 interleaved -> x (bf16, permuted) ============
    {
        const int b0 = 2 * w, b1 = 2 * w + 1;

        const float* wsaP = p.W_stats + lane * 6;
        const float* wsbP = p.W_stats + (lane + 32) * 6;
        float ws_a[6], ws_b[6];
        #pragma unroll
        for (int k = 0; k < 6; k++) { ws_a[k] = __ldg(wsaP + k); ws_b[k] = __ldg(wsbP + k); }
        float bs_a  = __ldg(p.b_stats + lane),  bs_b  = __ldg(p.b_stats + lane + 32);
        float gs_a  = __ldg(p.g_stats + lane),  gs_b  = __ldg(p.g_stats + lane + 32);
        float bes_a = __ldg(p.be_stats + lane), bes_b = __ldg(p.be_stats + lane + 32);
        float4 wb1v = __ldg((const float4*)(p.W_b1) + lane);
        float bb1 = __ldg(p.b_b1 + lane), gb1 = __ldg(p.g_b1 + lane), beb1 = __ldg(p.be_b1 + lane);
        float bb2 = __ldg(p.b_b2 + lane), gb2 = __ldg(p.g_b2 + lane), beb2 = __ldg(p.be_b2 + lane);

        float4 bxA = __ldg((const float4*)p.boxes + (box0 + b0));
        float4 bxB = __ldg((const float4*)p.boxes + (box0 + b1));
        float anA0 = fminf(fmaxf(bxA.x * (1.0f / 960.0f), 0.0f), 1.0f);
        float anA1 = fminf(fmaxf(bxA.y * (1.0f / 960.0f), 0.0f), 1.0f);
        float anA2 = fminf(fmaxf(bxA.z * (1.0f / 960.0f), 0.0f), 1.0f);
        float anA3 = fminf(fmaxf(bxA.w * (1.0f / 960.0f), 0.0f), 1.0f);
        float anB0 = fminf(fmaxf(bxB.x * (1.0f / 960.0f), 0.0f), 1.0f);
        float anB1 = fminf(fmaxf(bxB.y * (1.0f / 960.0f), 0.0f), 1.0f);
        float anB2 = fminf(fmaxf(bxB.z * (1.0f / 960.0f), 0.0f), 1.0f);
        float anB3 = fminf(fmaxf(bxB.w * (1.0f / 960.0f), 0.0f), 1.0f);

        int xA1 = min(max((int)floorf(anA0 * 60.0f), 0), GD - 1);
        int yA1 = min(max((int)floorf(anA1 * 60.0f), 0), GD - 1);
        int xA2 = min(max((int)ceilf(anA2 * 60.0f), xA1 + 1), GD);
        int yA2 = min(max((int)ceilf(anA3 * 60.0f), yA1 + 1), GD);
        int xB1 = min(max((int)floorf(anB0 * 60.0f), 0), GD - 1);
        int yB1 = min(max((int)floorf(anB1 * 60.0f), 0), GD - 1);
        int xB2 = min(max((int)ceilf(anB2 * 60.0f), xB1 + 1), GD);
        int yB2 = min(max((int)ceilf(anB3 * 60.0f), yB1 + 1), GD);
        int wdA = xA2 - xA1, areaA = wdA * (yA2 - yA1);
        int wdB = xB2 - xB1, areaB = wdB * (yB2 - yB1);
        int maxArea = max(areaA, areaB);
        float rwdA = __fdividef(1.0f, (float)wdA);
        float rwdB = __fdividef(1.0f, (float)wdB);

        float sA0 = 0.f, sA1 = 0.f, qA0 = 0.f, qA1 = 0.f;
        float mxA0 = -1e30f, mxA1 = -1e30f, mnA0 = 1e30f, mnA1 = 1e30f;
        float sB0 = 0.f, sB1 = 0.f, qB0 = 0.f, qB1 = 0.f;
        float mxB0 = -1e30f, mxB1 = -1e30f, mnB0 = 1e30f, mnB1 = 1e30f;

        for (int c = lane; c < maxArea; c += 32) {
            if (c < areaA) {
                int ry = (int)(((float)c + 0.5f) * rwdA);
                int idx = (yA1 + ry) * GD + xA1 + (c - ry * wdA);
                float v0 = __ldg(p.mv + idx);
                float v1 = __ldg(p.mv + GG + idx);
                sA0 += v0; qA0 += v0 * v0; mxA0 = fmaxf(mxA0, v0); mnA0 = fminf(mnA0, v0);
                sA1 += v1; qA1 += v1 * v1; mxA1 = fmaxf(mxA1, v1); mnA1 = fminf(mnA1, v1);
            }
            if (c < areaB) {
                int ry = (int)(((float)c + 0.5f) * rwdB);
                int idx = (yB1 + ry) * GD + xB1 + (c - ry * wdB);
                float v0 = __ldg(p.mv + idx);
                float v1 = __ldg(p.mv + GG + idx);
                sB0 += v0; qB0 += v0 * v0; mxB0 = fmaxf(mxB0, v0); mnB0 = fminf(mnB0, v0);
                sB1 += v1; qB1 += v1 * v1; mxB1 = fmaxf(mxB1, v1); mnB1 = fminf(mnB1, v1);
            }
        }
        #pragma unroll
        for (int o = 16; o; o >>= 1) {
            sA0 += __shfl_xor_sync(0xffffffffu, sA0, o);
            sA1 += __shfl_xor_sync(0xffffffffu, sA1, o);
            qA0 += __shfl_xor_sync(0xffffffffu, qA0, o);
            qA1 += __shfl_xor_sync(0xffffffffu, qA1, o);
            sB0 += __shfl_xor_sync(0xffffffffu, sB0, o);
            sB1 += __shfl_xor_sync(0xffffffffu, sB1, o);
            qB0 += __shfl_xor_sync(0xffffffffu, qB0, o);
            qB1 += __shfl_xor_sync(0xffffffffu, qB1, o);
            mxA0 = fmaxf(mxA0, __shfl_xor_sync(0xffffffffu, mxA0, o));
            mxA1 = fmaxf(mxA1, __shfl_xor_sync(0xffffffffu, mxA1, o));
            mnA0 = fminf(mnA0, __shfl_xor_sync(0xffffffffu, mnA0, o));
            mnA1 = fminf(mnA1, __shfl_xor_sync(0xffffffffu, mnA1, o));
            mxB0 = fmaxf(mxB0, __shfl_xor_sync(0xffffffffu, mxB0, o));
            mxB1 = fmaxf(mxB1, __shfl_xor_sync(0xffffffffu, mxB1, o));
            mnB0 = fminf(mnB0, __shfl_xor_sync(0xffffffffu, mnB0, o));
            mnB1 = fminf(mnB1, __shfl_xor_sync(0xffffffffu, mnB1, o));
        }
        float rcA = __fdividef(1.0f, (float)areaA);
        float rcB = __fdividef(1.0f, (float)areaB);
        float mA0 = sA0 * rcA, mA1 = sA1 * rcA;
        float mB0 = sB0 * rcB, mB1 = sB1 * rcB;
        float stA[6], stB[6];
        stA[0] = mA0; stA[1] = mA1;
        stA[2] = sqrtf(fmaxf(qA0 * rcA - mA0 * mA0, 0.0f));
        stA[3] = sqrtf(fmaxf(qA1 * rcA - mA1 * mA1, 0.0f));
        stA[4] = mxA0 - mnA0; stA[5] = mxA1 - mnA1;
        stB[0] = mB0; stB[1] = mB1;
        stB[2] = sqrtf(fmaxf(qB0 * rcB - mB0 * mB0, 0.0f));
        stB[3] = sqrtf(fmaxf(qB1 * rcB - mB1 * mB1, 0.0f));
        stB[4] = mxB0 - mnB0; stB[5] = mxB1 - mnB1;

        float zAa = bs_a, zAb = bs_b, zBa = bs_a, zBb = bs_b;
        #pragma unroll
        for (int k = 0; k < 6; k++) {
            zAa = fmaf(stA[k], ws_a[k], zAa);
            zAb = fmaf(stA[k], ws_b[k], zAb);
            zBa = fmaf(stB[k], ws_a[k], zBa);
            zBb = fmaf(stB[k], ws_b[k], zBb);
        }
        {
            float sA = zAa + zAb, qA = zAa * zAa + zAb * zAb;
            float sB = zBa + zBb, qB = zBa * zBa + zBb * zBb;
            #pragma unroll
            for (int o = 16; o; o >>= 1) {
                sA += __shfl_xor_sync(0xffffffffu, sA, o);
                qA += __shfl_xor_sync(0xffffffffu, qA, o);
                sB += __shfl_xor_sync(0xffffffffu, sB, o);
                qB += __shfl_xor_sync(0xffffffffu, qB, o);
            }
            float muA = sA * (1.0f / 64.0f);
            float invA = rsqrtf(fmaxf(qA * (1.0f / 64.0f) - muA * muA, 0.0f) + 1e-5f);
            float muB = sB * (1.0f / 64.0f);
            float invB = rsqrtf(fmaxf(qB * (1.0f / 64.0f) - muB * muB, 0.0f) + 1e-5f);
            float vA0 = fmaxf(fmaf((zAa - muA) * invA, gs_a, bes_a), 0.0f);
            float vA1 = fmaxf(fmaf((zAb - muA) * invA, gs_b, bes_b), 0.0f);
            float vB0 = fmaxf(fmaf((zBa - muB) * invB, gs_a, bes_a), 0.0f);
            float vB1 = fmaxf(fmaf((zBb - muB) * invB, gs_b, bes_b), 0.0f);
            int c0 = lane, c1 = lane + 32;
            x_h[(b0 * 52 + pk(c0 >> 1)) * 2 + (c0 & 1)] = __ushort_as_bfloat16(bf16b(vA0));
            x_h[(b0 * 52 + pk(c1 >> 1)) * 2 + (c1 & 1)] = __ushort_as_bfloat16(bf16b(vA1));
            x_h[(b1 * 52 + pk(c0 >> 1)) * 2 + (c0 & 1)] = __ushort_as_bfloat16(bf16b(vB0));
            x_h[(b1 * 52 + pk(c1 >> 1)) * 2 + (c1 & 1)] = __ushort_as_bfloat16(bf16b(vB1));
        }

        float tA = bb1, tB = bb1;
        tA = fmaf(anA0, wb1v.x, tA); tB = fmaf(anB0, wb1v.x, tB);
        tA = fmaf(anA1, wb1v.y, tA); tB = fmaf(anB1, wb1v.y, tB);
        tA = fmaf(anA2, wb1v.z, tA); tB = fmaf(anB2, wb1v.z, tB);
        tA = fmaf(anA3, wb1v.w, tA); tB = fmaf(anB3, wb1v.w, tB);
        {
            float sA = tA, qA = tA * tA, sB = tB, qB = tB * tB;
            #pragma unroll
            for (int o = 16; o; o >>= 1) {
                sA += __shfl_xor_sync(0xffffffffu, sA, o);
                qA += __shfl_xor_sync(0xffffffffu, qA, o);
                sB += __shfl_xor_sync(0xffffffffu, sB, o);
                qB += __shfl_xor_sync(0xffffffffu, qB, o);
            }
            float muA = sA * (1.0f / 32.0f);
            float invA = rsqrtf(fmaxf(qA * (1.0f / 32.0f) - muA * muA, 0.0f) + 1e-5f);
            float muB = sB * (1.0f / 32.0f);
            float invB = rsqrtf(fmaxf(qB * (1.0f / 32.0f) - muB * muB, 0.0f) + 1e-5f);
            hwarp[b0 * 32 + lane] = fmaxf(fmaf((tA - muA) * invA, gb1, beb1), 0.0f);
            hwarp[b1 * 32 + lane] = fmaxf(fmaf((tB - muB) * invB, gb1, beb1), 0.0f);
        }
        __syncwarp();
        float tA0 = bb2, tA1 = 0.0f, tB0 = bb2, tB1 = 0.0f;
        const float* wb2 = p.W_b2 + lane * 32;
        #pragma unroll
        for (int k4 = 0; k4 < 8; k4 += 2) {
            float4 wva = __ldg((const float4*)wb2 + k4);
            float4 wvb = __ldg((const float4*)wb2 + k4 + 1);
            const float* hpA = hwarp + b0 * 32 + 4 * k4;
            const float* hpB = hwarp + b1 * 32 + 4 * k4;
            tA0 = fmaf(hpA[0], wva.x, tA0); tB0 = fmaf(hpB[0], wva.x, tB0);
            tA0 = fmaf(hpA[1], wva.y, tA0); tB0 = fmaf(hpB[1], wva.y, tB0);
            tA0 = fmaf(hpA[2], wva.z, tA0); tB0 = fmaf(hpB[2], wva.z, tB0);
            tA0 = fmaf(hpA[3], wva.w, tA0); tB0 = fmaf(hpB[3], wva.w, tB0);
            tA1 = fmaf(hpA[4], wvb.x, tA1); tB1 = fmaf(hpB[4], wvb.x, tB1);
            tA1 = fmaf(hpA[5], wvb.y, tA1); tB1 = fmaf(hpB[5], wvb.y, tB1);
            tA1 = fmaf(hpA[6], wvb.z, tA1); tB1 = fmaf(hpB[6], wvb.z, tB1);
            tA1 = fmaf(hpA[7], wvb.w, tA1); tB1 = fmaf(hpB[7], wvb.w, tB1);
        }
        __syncwarp();
        {
            float t2A = tA0 + tA1, t2B = tB0 + tB1;
            float sA = t2A, qA = t2A * t2A, sB = t2B, qB = t2B * t2B;
            #pragma unroll
            for (int o = 16; o; o >>= 1) {
                sA += __shfl_xor_sync(0xffffffffu, sA, o);
                qA += __shfl_xor_sync(0xffffffffu, qA, o);
                sB += __shfl_xor_sync(0xffffffffu, sB, o);
                qB += __shfl_xor_sync(0xffffffffu, qB, o);
            }
            float muA = sA * (1.0f / 32.0f);
            float invA = rsqrtf(fmaxf(qA * (1.0f / 32.0f) - muA * muA, 0.0f) + 1e-5f);
            float muB = sB * (1.0f / 32.0f);
            float invB = rsqrtf(fmaxf(qB * (1.0f / 32.0f) - muB * muB, 0.0f) + 1e-5f);
            float vA = fmaxf(fmaf((t2A - muA) * invA, gb2, beb2), 0.0f);
            float vB = fmaxf(fmaf((t2B - muB) * invB, gb2, beb2), 0.0f);
            int c2 = 64 + lane;
            x_h[(b0 * 52 + pk(c2 >> 1)) * 2 + (c2 & 1)] = __ushort_as_bfloat16(bf16b(vA));
            x_h[(b1 * 52 + pk(c2 >> 1)) * 2 + (c2 & 1)] = __ushort_as_bfloat16(bf16b(vB));
        }
    }

    asm volatile("cp.async.wait_group 0;");
    __syncthreads();   // x complete + all weight tiles staged

    // ============ Gates GEMM via bf16 mma (k16): 6 k-steps ============
    const int mt = w & 1;
    const int ng = w >> 1;        // 0..7
    const int m0 = mt * 16;

    float dacc[6][4];
    #pragma unroll
    for (int j = 0; j < 6; j++)
        #pragma unroll
        for (int q = 0; q < 4; q++) dacc[j][q] = 0.0f;

    #pragma unroll
    for (int ks = 0; ks < 6; ks++) {
        int k0 = 8 * ks;
        uint2 aA = *(const uint2*)(x_u + (m0 + gid) * 52 + k0 + 2 * tig);
        uint2 aB = *(const uint2*)(x_u + (m0 + gid + 8) * 52 + k0 + 2 * tig);
        #pragma unroll
        for (int j = 0; j < 6; j++) {
            int n = ng * 48 + 8 * j + gid;
            uint2 bv = *(const uint2*)(wg_u + n * 52 + k0 + 2 * tig);
            mma_bf16(dacc[j], aA.x, aB.x, aA.y, aB.y, bv.x, bv.y);
        }
    }

    // ============ LSTM fully in registers -> h (bf16 pairs, permuted) ============
    #pragma unroll
    for (int jj = 0; jj < 2; jj++) {
        int u0 = 16 * ng + 8 * jj + 2 * tig;
        int jp = pk(u0 >> 1);
        float bi0 = __ldg(g_bias + u0),       bi1 = __ldg(g_bias + u0 + 1);
        float bg0 = __ldg(g_bias + 128 + u0), bg1 = __ldg(g_bias + 128 + u0 + 1);
        float bo0 = __ldg(g_bias + 256 + u0), bo1 = __ldg(g_bias + 256 + u0 + 1);
        {
            float c0 = sigfast(dacc[3 * jj + 0][0] + bi0) * tanhfast(dacc[3 * jj + 1][0] + bg0);
            float h0 = sigfast(dacc[3 * jj + 2][0] + bo0) * tanhfast(c0);
            float c1 = sigfast(dacc[3 * jj + 0][1] + bi1) * tanhfast(dacc[3 * jj + 1][1] + bg1);
            float h1 = sigfast(dacc[3 * jj + 2][1] + bo1) * tanhfast(c1);
            h_u[(m0 + gid) * 68 + jp] = bf16pack(h0, h1);
        }
        {
            float c0 = sigfast(dacc[3 * jj + 0][2] + bi0) * tanhfast(dacc[3 * jj + 1][2] + bg0);
            float h0 = sigfast(dacc[3 * jj + 2][2] + bo0) * tanhfast(c0);
            float c1 = sigfast(dacc[3 * jj + 0][3] + bi1) * tanhfast(dacc[3 * jj + 1][3] + bg1);
            float h1 = sigfast(dacc[3 * jj + 2][3] + bo1) * tanhfast(c1);
            h_u[(m0 + gid + 8) * 68 + jp] = bf16pack(h0, h1);
        }
    }
    __syncthreads();   // h visible

    // ============ Heads GEMM via bf16 mma: 8 k-steps ============
    float hacc[3][4];
    #pragma unroll
    for (int j = 0; j < 3; j++)
        #pragma unroll
        for (int q = 0; q < 4; q++) hacc[j][q] = 0.0f;

    #pragma unroll
    for (int ks = 0; ks < 8; ks++) {
        int k0 = 8 * ks;
        uint2 aA = *(const uint2*)(h_u + (m0 + gid) * 68 + k0 + 2 * tig);
        uint2 aB = *(const uint2*)(h_u + (m0 + gid + 8) * 68 + k0 + 2 * tig);
        #pragma unroll
        for (int j = 0; j < 3; j++) {
            int n = ng * 24 + 8 * j + gid;
            uint2 bv = *(const uint2*)(wh_u + n * 68 + k0 + 2 * tig);
            mma_bf16(hacc[j], aA.x, aB.x, aA.y, aB.y, bv.x, bv.y);
        }
    }

    // ---- epilogue: bias + relu -> hid (bf16 pairs, permuted) ----
    #pragma unroll
    for (int j = 0; j < 3; j++) {
        int nc = ng * 24 + 8 * j + 2 * tig;
        float bias0 = (nc < 64) ? __ldg(p.b_p1 + nc)
                    : (nc < 128) ? __ldg(p.b_s1 + nc - 64)
                                 : __ldg(p.b_c1 + nc - 128);
        int nc1 = nc + 1;
        float bias1 = (nc1 < 64) ? __ldg(p.b_p1 + nc1)
                    : (nc1 < 128) ? __ldg(p.b_s1 + nc1 - 64)
                                  : __ldg(p.b_c1 + nc1 - 128);
        int jp = pk(nc >> 1);
        hid_u[(m0 + gid) * 100 + jp] =
            bf16pack(fmaxf(hacc[j][0] + bias0, 0.0f), fmaxf(hacc[j][1] + bias1, 0.0f));
        hid_u[(m0 + gid + 8) * 100 + jp] =
            bf16pack(fmaxf(hacc[j][2] + bias0, 0.0f), fmaxf(hacc[j][3] + bias1, 0.0f));
    }
    __syncthreads();

    // ============ Head-2 layer: one bf16 MMA set (warps 0,1) ============
    if (w < 2) {
        const int m02 = w * 16;
        float f2[4] = {0.0f, 0.0f, 0.0f, 0.0f};
        #pragma unroll
        for (int ks = 0; ks < 12; ks++) {
            int k0 = 8 * ks;
            uint2 aA = *(const uint2*)(hid_u + (m02 + gid) * 100 + k0 + 2 * tig);
            uint2 aB = *(const uint2*)(hid_u + (m02 + gid + 8) * 100 + k0 + 2 * tig);
            uint2 bv = *(const uint2*)(w2_u + gid * 100 + k0 + 2 * tig);
            mma_bf16(f2, aA.x, aB.x, aA.y, aB.y, bv.x, bv.y);
        }
        int c0 = 2 * tig;
        if (c0 < 5) {
            float bias = (c0 == 0) ? __ldg(p.b_p2)
                       : (c0 == 2) ? __ldg(p.b_s2)
                                   : __ldg(p.b_c2);
            fin_s[(m02 + gid) * 5 + c0]     = f2[0] + bias;
            fin_s[(m02 + gid + 8) * 5 + c0] = f2[2] + bias;
        }
        int c1 = c0 + 1;
        if (c1 < 5) {
            float bias = (c1 == 1) ? __ldg(p.b_p2 + 1)
                       : (c1 == 3) ? __ldg(p.b_s2 + 1)
                                   : __ldg(p.b_c2);
            fin_s[(m02 + gid) * 5 + c1]     = f2[1] + bias;
            fin_s[(m02 + gid + 8) * 5 + c1] = f2[3] + bias;
        }
    }
    __syncthreads();

    // ============ Decode + output ============
    if (tid < 32) {
        int b = tid;
        float4 bx = __ldg((const float4*)p.boxes + (box0 + b));
        float cx = (bx.x + bx.z) * 0.5f, cy = (bx.y + bx.w) * 0.5f;
        float wd = bx.z - bx.x, hg = bx.w - bx.y;
        float ncx = cx + fin_s[b * 5 + 0];
        float ncy = cy + fin_s[b * 5 + 1];
        float nw = wd * __expf(fin_s[b * 5 + 2]);
        float nh = hg * __expf(fin_s[b * 5 + 3]);
        float conf = __fdividef(1.0f, 1.0f + __expf(-fin_s[b * 5 + 4]));
        float* op = p.out + (box0 + b) * 5;
        op[0] = ncx - nw * 0.5f;
        op[1] = ncy - nh * 0.5f;
        op[2] = ncx + nw * 0.5f;
        op[3] = ncy + nh * 0.5f;
        op[4] = conf;
    }
}

extern "C" void kernel_launch(void* const* d_in, const int* in_sizes, int n_in,
                              void* d_out, int out_size) {
    (void)in_sizes; (void)n_in; (void)out_size;
    Params p;
    p.mv       = (const float*)d_in[0];
    p.boxes    = (const float*)d_in[1];
    p.W_stats  = (const float*)d_in[2];
    p.b_stats  = (const float*)d_in[3];
    p.g_stats  = (const float*)d_in[4];
    p.be_stats = (const float*)d_in[5];
    p.W_b1     = (const float*)d_in[6];
    p.b_b1     = (const float*)d_in[7];
    p.g_b1     = (const float*)d_in[8];
    p.be_b1    = (const float*)d_in[9];
    p.W_b2     = (const float*)d_in[10];
    p.b_b2     = (const float*)d_in[11];
    p.g_b2     = (const float*)d_in[12];
    p.be_b2    = (const float*)d_in[13];
    p.W_ih     = (const float*)d_in[14];
    p.W_hh     = (const float*)d_in[15];
    p.b_ih     = (const float*)d_in[16];
    p.b_hh     = (const float*)d_in[17];
    p.W_p1     = (const float*)d_in[18];
    p.b_p1     = (const float*)d_in[19];
    p.W_p2     = (const float*)d_in[20];
    p.b_p2     = (const float*)d_in[21];
    p.W_s1     = (const float*)d_in[22];
    p.b_s1     = (const float*)d_in[23];
    p.W_s2     = (const float*)d_in[24];
    p.b_s2     = (const float*)d_in[25];
    p.W_c1     = (const float*)d_in[26];
    p.b_c1     = (const float*)d_in[27];
    p.W_c2     = (const float*)d_in[28];
    p.b_c2     = (const float*)d_in[29];
    p.out      = (float*)d_out;

    prep_kernel<<<128, 256>>>(p);
    cudaFuncSetAttribute(tracker_fused_kernel,
                         cudaFuncAttributeMaxDynamicSharedMemorySize, SMEM_BYTES);
    tracker_fused_kernel<<<128, NT, SMEM_BYTES>>>(p);
}